// round 3
// baseline (speedup 1.0000x reference)
#include <cuda_runtime.h>
#include <cuda_bf16.h>
#include <math.h>

// ----------------------------------------------------------------------------
// Problem constants (match reference)
// ----------------------------------------------------------------------------
#define NN      50000
#define EE      800000
#define NEDGE   (EE + NN)       // with self loops = 850000
#define NGRAPH  64
#define HC12    256             // heads*ch layers 1,2
#define HC3     64              // layer 3
#define NEG_SLOPE 0.2f
#define EPSV    1e-16f

// ----------------------------------------------------------------------------
// Device scratch (static globals — no allocation allowed). 256B aligned for
// vector access paths.
// ----------------------------------------------------------------------------
__device__ __align__(256) float g_h   [(size_t)NN * HC12];   // gemm output
__device__ __align__(256) float g_agg [(size_t)NN * HC12];   // aggregation output
__device__ __align__(256) float g_als [NN * 4];
__device__ __align__(256) float g_ald [NN * 4];
__device__ __align__(256) float g_m   [NN * 4];
__device__ __align__(256) float g_s   [NN * 4];
__device__ __align__(256) int   g_src [NEDGE];
__device__ __align__(256) int   g_dst [NEDGE];
__device__ __align__(256) int   g_batch[NN];
__device__ __align__(256) float g_pool[NGRAPH * HC3];
__device__ __align__(256) float g_cnt [NGRAPH];
__device__ int g_is64;   // 1 if index inputs are int64, 0 if int32

// ----------------------------------------------------------------------------
// Helpers
// ----------------------------------------------------------------------------
__device__ __forceinline__ float lrelu(float x) {
    return x >= 0.f ? x : NEG_SLOPE * x;
}

__device__ __forceinline__ void atomicMaxF(float* addr, float v) {
    if (v >= 0.f) atomicMax((int*)addr, __float_as_int(v));
    else          atomicMin((unsigned int*)addr, __float_as_uint(v));
}

// ----------------------------------------------------------------------------
// Dtype probe: edge values are uniform random in [0, 50000). If stored as
// little-endian int64, every odd 32-bit word is a zero high-half. If stored
// as int32, the odd words are random values (P(all 64 == 0) ~ 0).
// ----------------------------------------------------------------------------
__global__ void detect_dtype(const unsigned int* __restrict__ w) {
    if (threadIdx.x == 0 && blockIdx.x == 0) {
        int all0 = 1;
        for (int i = 1; i < 128; i += 2)
            if (w[i] != 0u) { all0 = 0; break; }
        g_is64 = all0;
    }
}

// ----------------------------------------------------------------------------
// Edge index conversion -> int32 src/dst with self-loops appended
// ----------------------------------------------------------------------------
__global__ void conv_edges(const void* __restrict__ ei_raw,
                           int* __restrict__ src, int* __restrict__ dst) {
    int i = blockIdx.x * blockDim.x + threadIdx.x;
    if (i >= NEDGE) return;
    if (i >= EE) {
        int v = i - EE;
        src[i] = v;
        dst[i] = v;
        return;
    }
    if (g_is64) {
        const long long* e = (const long long*)ei_raw;
        src[i] = (int)e[i];
        dst[i] = (int)e[EE + i];
    } else {
        const int* e = (const int*)ei_raw;
        src[i] = e[i];
        dst[i] = e[EE + i];
    }
}

// batch -> int32
__global__ void conv_batch(const void* __restrict__ b_raw, int* __restrict__ bo) {
    int i = blockIdx.x * blockDim.x + threadIdx.x;
    if (i >= NN) return;
    bo[i] = g_is64 ? (int)((const long long*)b_raw)[i] : ((const int*)b_raw)[i];
}

// ----------------------------------------------------------------------------
// Zero a float buffer (float4 grid-stride)
// ----------------------------------------------------------------------------
__global__ void zero_f4(float4* __restrict__ p, int n4) {
    int i = blockIdx.x * blockDim.x + threadIdx.x;
    int stride = gridDim.x * blockDim.x;
    float4 z = make_float4(0.f, 0.f, 0.f, 0.f);
    for (; i < n4; i += stride) p[i] = z;
}

// ----------------------------------------------------------------------------
// SGEMM: C[M,Ncols] = A[M,K] @ B[K,Ncols]
// BM=128, BK=8, TM=8, BN/TN templated. 256 threads.
// ----------------------------------------------------------------------------
template <int BN, int TN>
__global__ void sgemm(const float* __restrict__ A, const float* __restrict__ B,
                      float* __restrict__ C, int M, int K, int Ncols) {
    const int BM = 128, BK = 8, TM = 8;
    __shared__ alignas(16) float As[BK][BM];
    __shared__ alignas(16) float Bs[BK][BN];

    int tid = threadIdx.x;
    int mBlock = blockIdx.x * BM;
    int nBlock = blockIdx.y * BN;

    const int TCOLS = BN / TN;
    int tcol = tid % TCOLS;
    int trow = tid / TCOLS;

    float acc[TM][TN];
#pragma unroll
    for (int i = 0; i < TM; i++)
#pragma unroll
        for (int j = 0; j < TN; j++) acc[i][j] = 0.f;

    int aRow = tid >> 1;
    int aCol = (tid & 1) * 4;
    int bRow = tid / (BN / 4);
    int bCol = (tid % (BN / 4)) * 4;

    for (int k0 = 0; k0 < K; k0 += BK) {
        float4 av = make_float4(0.f, 0.f, 0.f, 0.f);
        int gr = mBlock + aRow;
        if (gr < M) av = *(const float4*)(A + (size_t)gr * K + k0 + aCol);
        As[aCol + 0][aRow] = av.x;
        As[aCol + 1][aRow] = av.y;
        As[aCol + 2][aRow] = av.z;
        As[aCol + 3][aRow] = av.w;

        if (tid < 2 * BN) {
            float4 bv = *(const float4*)(B + (size_t)(k0 + bRow) * Ncols + nBlock + bCol);
            *(float4*)&Bs[bRow][bCol] = bv;
        }
        __syncthreads();

#pragma unroll
        for (int kk = 0; kk < BK; kk++) {
            float ra[TM], rb[TN];
#pragma unroll
            for (int i = 0; i < TM; i++) ra[i] = As[kk][trow * TM + i];
#pragma unroll
            for (int j = 0; j < TN; j++) rb[j] = Bs[kk][tcol * TN + j];
#pragma unroll
            for (int i = 0; i < TM; i++)
#pragma unroll
                for (int j = 0; j < TN; j++) acc[i][j] += ra[i] * rb[j];
        }
        __syncthreads();
    }

#pragma unroll
    for (int i = 0; i < TM; i++) {
        int row = mBlock + trow * TM + i;
        if (row < M) {
            float* cp = C + (size_t)row * Ncols + nBlock + tcol * TN;
#pragma unroll
            for (int j = 0; j < TN; j++) cp[j] = acc[i][j];
        }
    }
}

// ----------------------------------------------------------------------------
// attn_prep: per (node, head) compute al_src, al_dst dot products; init m, s
// warp per (node*H + head)
// ----------------------------------------------------------------------------
template <int H, int C>
__global__ void attn_prep(const float* __restrict__ h,
                          const float* __restrict__ a_src,
                          const float* __restrict__ a_dst,
                          float* __restrict__ als, float* __restrict__ ald,
                          float* __restrict__ m, float* __restrict__ s) {
    int w = (blockIdx.x * blockDim.x + threadIdx.x) >> 5;
    int lane = threadIdx.x & 31;
    if (w >= NN * H) return;
    int node = w / H;
    int head = w % H;

    const float* hp = h + (size_t)node * (H * C) + head * C;
    float d1 = 0.f, d2 = 0.f;
#pragma unroll
    for (int i = lane; i < C; i += 32) {
        float v = hp[i];
        d1 += v * a_src[head * C + i];
        d2 += v * a_dst[head * C + i];
    }
#pragma unroll
    for (int off = 16; off > 0; off >>= 1) {
        d1 += __shfl_down_sync(0xffffffffu, d1, off);
        d2 += __shfl_down_sync(0xffffffffu, d2, off);
    }
    if (lane == 0) {
        als[node * H + head] = d1;
        ald[node * H + head] = d2;
        m[node * H + head] = -INFINITY;
        s[node * H + head] = 0.f;
    }
}

// ----------------------------------------------------------------------------
// Pass 1: segment max over dst
// ----------------------------------------------------------------------------
template <int H>
__global__ void edge_max(const int* __restrict__ src, const int* __restrict__ dst,
                         const float* __restrict__ als, const float* __restrict__ ald,
                         float* __restrict__ m) {
    int e = blockIdx.x * blockDim.x + threadIdx.x;
    if (e >= NEDGE) return;
    int s0 = src[e], d0 = dst[e];
#pragma unroll
    for (int hh = 0; hh < H; hh++) {
        float v = lrelu(als[s0 * H + hh] + ald[d0 * H + hh]);
        atomicMaxF(&m[d0 * H + hh], v);
    }
}

// ----------------------------------------------------------------------------
// Pass 2: segment sum of exp(e - m[dst])
// ----------------------------------------------------------------------------
template <int H>
__global__ void edge_sumexp(const int* __restrict__ src, const int* __restrict__ dst,
                            const float* __restrict__ als, const float* __restrict__ ald,
                            const float* __restrict__ m, float* __restrict__ s) {
    int e = blockIdx.x * blockDim.x + threadIdx.x;
    if (e >= NEDGE) return;
    int s0 = src[e], d0 = dst[e];
#pragma unroll
    for (int hh = 0; hh < H; hh++) {
        float v = lrelu(als[s0 * H + hh] + ald[d0 * H + hh]);
        atomicAdd(&s[d0 * H + hh], __expf(v - m[d0 * H + hh]));
    }
}

// ----------------------------------------------------------------------------
// Pass 3: out[dst] += h[src] * alpha     (warp per edge)
// ----------------------------------------------------------------------------
template <int H, int C>
__global__ void edge_msg(const int* __restrict__ src, const int* __restrict__ dst,
                         const float* __restrict__ h,
                         const float* __restrict__ als, const float* __restrict__ ald,
                         const float* __restrict__ m, const float* __restrict__ s,
                         float* __restrict__ out) {
    const int TOTAL = H * C;
    const int VE = TOTAL / 32;
    int w = (blockIdx.x * blockDim.x + threadIdx.x) >> 5;
    int lane = threadIdx.x & 31;
    if (w >= NEDGE) return;
    int s0 = src[w], d0 = dst[w];

    int base = lane * VE;
    int head = base / C;

    float e = lrelu(als[s0 * H + head] + ald[d0 * H + head]);
    float alpha = __expf(e - m[d0 * H + head]) / (s[d0 * H + head] + EPSV);

    const float* hp = h + (size_t)s0 * TOTAL + base;
    float* op = out + (size_t)d0 * TOTAL + base;

    if (VE >= 4) {
#pragma unroll
        for (int i = 0; i < VE / 4; i++) {
            float4 v = *(const float4*)(hp + i * 4);
            float4 r = make_float4(v.x * alpha, v.y * alpha, v.z * alpha, v.w * alpha);
            atomicAdd((float4*)(op + i * 4), r);
        }
    } else {
        float2 v = *(const float2*)hp;
        float2 r = make_float2(v.x * alpha, v.y * alpha);
        atomicAdd((float2*)op, r);
    }
}

// ----------------------------------------------------------------------------
// bias + optional relu (in place)
// ----------------------------------------------------------------------------
template <int COLS, bool RELU>
__global__ void bias_act(float* __restrict__ x, const float* __restrict__ b, int total) {
    int i = blockIdx.x * blockDim.x + threadIdx.x;
    if (i >= total) return;
    float v = x[i] + b[i & (COLS - 1)];
    x[i] = RELU ? fmaxf(v, 0.f) : v;
}

// ----------------------------------------------------------------------------
// Per-graph counts via binary search on sorted batch (int32)
// ----------------------------------------------------------------------------
__global__ void counts_k(const int* __restrict__ batch, float* __restrict__ cnt) {
    int g = threadIdx.x;
    if (g >= NGRAPH) return;
    int lo = 0, hi = NN;
    while (lo < hi) { int mid = (lo + hi) >> 1; if (batch[mid] < g) lo = mid + 1; else hi = mid; }
    int a = lo;
    lo = 0; hi = NN;
    while (lo < hi) { int mid = (lo + hi) >> 1; if (batch[mid] < g + 1) lo = mid + 1; else hi = mid; }
    cnt[g] = (float)(lo - a);
}

// ----------------------------------------------------------------------------
// Pooling: segment sum over sorted batch, run-length accumulation
// ----------------------------------------------------------------------------
__global__ void pool_sum(const float* __restrict__ h, const int* __restrict__ batch,
                         float* __restrict__ pool) {
    int c = threadIdx.x & 63;
    int r = threadIdx.x >> 6;
    int start = blockIdx.x * 1024;
    int end = start + 1024;
    if (end > NN) end = NN;
    int cur = -1;
    float acc = 0.f;
    for (int nd = start + r; nd < end; nd += 4) {
        int g = batch[nd];
        if (g != cur) {
            if (cur >= 0) atomicAdd(&pool[cur * 64 + c], acc);
            cur = g;
            acc = 0.f;
        }
        acc += h[(size_t)nd * 64 + c];
    }
    if (cur >= 0) atomicAdd(&pool[cur * 64 + c], acc);
}

// ----------------------------------------------------------------------------
// Final: out[g] = (pool[g]/cnt[g] + b3) @ lin_W + lin_b
// ----------------------------------------------------------------------------
__global__ void final_k(const float* __restrict__ pool, const float* __restrict__ cnt,
                        const float* __restrict__ b3,
                        const float* __restrict__ linW, const float* __restrict__ linb,
                        float* __restrict__ out) {
    int g = blockIdx.x;
    int j = threadIdx.x;
    __shared__ float mean[64];
    float cc = fmaxf(cnt[g], 1.f);
    mean[j] = pool[g * 64 + j] / cc + b3[j];
    __syncthreads();
    float acc = 0.f;
#pragma unroll
    for (int k = 0; k < 64; k++) acc += mean[k] * linW[k * 64 + j];
    out[g * 64 + j] = acc + linb[j];
}

// ----------------------------------------------------------------------------
// Host launcher
// ----------------------------------------------------------------------------
extern "C" void kernel_launch(void* const* d_in, const int* in_sizes, int n_in,
                              void* d_out, int out_size) {
    const float* x     = (const float*)d_in[0];
    const void*  ei    = d_in[1];        // int32 or int64 — probed on device
    // d_in[2] = edge_attr (unused)
    const void*  batch = d_in[3];
    const float* W1  = (const float*)d_in[4];
    const float* a1s = (const float*)d_in[5];
    const float* a1d = (const float*)d_in[6];
    const float* b1  = (const float*)d_in[7];
    const float* W2  = (const float*)d_in[8];
    const float* a2s = (const float*)d_in[9];
    const float* a2d = (const float*)d_in[10];
    const float* b2  = (const float*)d_in[11];
    const float* W3  = (const float*)d_in[12];
    const float* a3s = (const float*)d_in[13];
    const float* a3d = (const float*)d_in[14];
    const float* b3  = (const float*)d_in[15];
    const float* lW  = (const float*)d_in[16];
    const float* lb  = (const float*)d_in[17];
    float* out = (float*)d_out;

    float *p_h, *p_agg, *p_als, *p_ald, *p_m, *p_s, *p_pool, *p_cnt;
    int *p_src, *p_dst, *p_batch;
    cudaGetSymbolAddress((void**)&p_h,    g_h);
    cudaGetSymbolAddress((void**)&p_agg,  g_agg);
    cudaGetSymbolAddress((void**)&p_als,  g_als);
    cudaGetSymbolAddress((void**)&p_ald,  g_ald);
    cudaGetSymbolAddress((void**)&p_m,    g_m);
    cudaGetSymbolAddress((void**)&p_s,    g_s);
    cudaGetSymbolAddress((void**)&p_src,  g_src);
    cudaGetSymbolAddress((void**)&p_dst,  g_dst);
    cudaGetSymbolAddress((void**)&p_batch,g_batch);
    cudaGetSymbolAddress((void**)&p_pool, g_pool);
    cudaGetSymbolAddress((void**)&p_cnt,  g_cnt);

    const int TB = 256;
    const int edgeBlocks = (NEDGE + TB - 1) / TB;
    const int edgeWarpBlocks = (NEDGE * 32 + TB - 1) / TB;
    const int mTiles = (NN + 127) / 128;

    // --- dtype probe + index conversion (+ self loops) ---
    detect_dtype<<<1, 32>>>((const unsigned int*)ei);
    conv_edges<<<edgeBlocks, TB>>>(ei, p_src, p_dst);
    conv_batch<<<(NN + TB - 1) / TB, TB>>>(batch, p_batch);

    // ================= Layer 1: 128 -> 4x64 =================
    {
        dim3 grid(mTiles, HC12 / 128);
        sgemm<128, 8><<<grid, TB>>>(x, W1, p_h, NN, 128, HC12);
        attn_prep<4, 64><<<(NN * 4 * 32 + TB - 1) / TB, TB>>>(p_h, a1s, a1d, p_als, p_ald, p_m, p_s);
        edge_max<4><<<edgeBlocks, TB>>>(p_src, p_dst, p_als, p_ald, p_m);
        edge_sumexp<4><<<edgeBlocks, TB>>>(p_src, p_dst, p_als, p_ald, p_m, p_s);
        zero_f4<<<4096, TB>>>((float4*)p_agg, NN * HC12 / 4);
        edge_msg<4, 64><<<edgeWarpBlocks, TB>>>(p_src, p_dst, p_h, p_als, p_ald, p_m, p_s, p_agg);
        bias_act<HC12, true><<<(NN * HC12 + TB - 1) / TB, TB>>>(p_agg, b1, NN * HC12);
    }

    // ================= Layer 2: 256 -> 4x64 =================
    {
        dim3 grid(mTiles, HC12 / 128);
        sgemm<128, 8><<<grid, TB>>>(p_agg, W2, p_h, NN, HC12, HC12);
        attn_prep<4, 64><<<(NN * 4 * 32 + TB - 1) / TB, TB>>>(p_h, a2s, a2d, p_als, p_ald, p_m, p_s);
        edge_max<4><<<edgeBlocks, TB>>>(p_src, p_dst, p_als, p_ald, p_m);
        edge_sumexp<4><<<edgeBlocks, TB>>>(p_src, p_dst, p_als, p_ald, p_m, p_s);
        zero_f4<<<4096, TB>>>((float4*)p_agg, NN * HC12 / 4);
        edge_msg<4, 64><<<edgeWarpBlocks, TB>>>(p_src, p_dst, p_h, p_als, p_ald, p_m, p_s, p_agg);
        bias_act<HC12, true><<<(NN * HC12 + TB - 1) / TB, TB>>>(p_agg, b2, NN * HC12);
    }

    // ================= Layer 3: 256 -> 1x64 =================
    {
        dim3 grid(mTiles, 1);
        sgemm<64, 4><<<grid, TB>>>(p_agg, W3, p_h, NN, HC12, HC3);
        attn_prep<1, 64><<<(NN * 32 + TB - 1) / TB, TB>>>(p_h, a3s, a3d, p_als, p_ald, p_m, p_s);
        edge_max<1><<<edgeBlocks, TB>>>(p_src, p_dst, p_als, p_ald, p_m);
        edge_sumexp<1><<<edgeBlocks, TB>>>(p_src, p_dst, p_als, p_ald, p_m, p_s);
        zero_f4<<<2048, TB>>>((float4*)p_agg, NN * HC3 / 4);
        edge_msg<1, 64><<<edgeWarpBlocks, TB>>>(p_src, p_dst, p_h, p_als, p_ald, p_m, p_s, p_agg);
    }

    // ================= Pool + final linear =================
    zero_f4<<<4, 64>>>((float4*)p_pool, NGRAPH * HC3 / 4);
    zero_f4<<<1, 64>>>((float4*)p_cnt, NGRAPH / 4);
    counts_k<<<1, 64>>>(p_batch, p_cnt);
    pool_sum<<<(NN + 1023) / 1024, 256>>>(p_agg, p_batch, p_pool);
    final_k<<<NGRAPH, 64>>>(p_pool, p_cnt, b3, lW, lb, out);
}

// round 4
// speedup vs baseline: 1.1193x; 1.1193x over previous
#include <cuda_runtime.h>
#include <cuda_bf16.h>
#include <math.h>

// ----------------------------------------------------------------------------
// Problem constants
// ----------------------------------------------------------------------------
#define NN      50000
#define EE      800000
#define NEDGE   (EE + NN)       // with self loops = 850000
#define NGRAPH  64
#define HC12    256             // heads*ch layers 1,2
#define HC3     64              // layer 3
#define NEG_SLOPE 0.2f
#define EPSV    1e-16f

// ----------------------------------------------------------------------------
// Device scratch
// ----------------------------------------------------------------------------
__device__ __align__(256) float g_h   [(size_t)NN * HC12];
__device__ __align__(256) float g_agg [(size_t)NN * HC12];
__device__ __align__(256) float g_als [NN * 4];
__device__ __align__(256) float g_ald [NN * 4];
__device__ __align__(256) float g_s   [NN * 4];
__device__ __align__(256) int   g_src [NEDGE];
__device__ __align__(256) int   g_dst [NEDGE];
__device__ __align__(256) int   g_batch[NN];
__device__ __align__(256) float g_pool[NGRAPH * HC3];
__device__ __align__(256) float g_cnt [NGRAPH];
__device__ int   g_is64;
__device__ float g_maxs;   // global max of als
__device__ float g_maxd;   // global max of ald

// ----------------------------------------------------------------------------
// Helpers
// ----------------------------------------------------------------------------
__device__ __forceinline__ float lrelu(float x) {
    return x >= 0.f ? x : NEG_SLOPE * x;
}

__device__ __forceinline__ void atomicMaxF(float* addr, float v) {
    if (v >= 0.f) atomicMax((int*)addr, __float_as_int(v));
    else          atomicMin((unsigned int*)addr, __float_as_uint(v));
}

// ----------------------------------------------------------------------------
// Dtype probe (int32 vs int64 indices)
// ----------------------------------------------------------------------------
__global__ void detect_dtype(const unsigned int* __restrict__ w) {
    if (threadIdx.x == 0 && blockIdx.x == 0) {
        int all0 = 1;
        for (int i = 1; i < 128; i += 2)
            if (w[i] != 0u) { all0 = 0; break; }
        g_is64 = all0;
    }
}

__global__ void conv_edges(const void* __restrict__ ei_raw,
                           int* __restrict__ src, int* __restrict__ dst) {
    int i = blockIdx.x * blockDim.x + threadIdx.x;
    if (i >= NEDGE) return;
    if (i >= EE) {
        int v = i - EE;
        src[i] = v; dst[i] = v;
        return;
    }
    if (g_is64) {
        const long long* e = (const long long*)ei_raw;
        src[i] = (int)e[i];
        dst[i] = (int)e[EE + i];
    } else {
        const int* e = (const int*)ei_raw;
        src[i] = e[i];
        dst[i] = e[EE + i];
    }
}

__global__ void conv_batch(const void* __restrict__ b_raw, int* __restrict__ bo) {
    int i = blockIdx.x * blockDim.x + threadIdx.x;
    if (i >= NN) return;
    bo[i] = g_is64 ? (int)((const long long*)b_raw)[i] : ((const int*)b_raw)[i];
}

__global__ void zero_f4(float4* __restrict__ p, int n4) {
    int i = blockIdx.x * blockDim.x + threadIdx.x;
    int stride = gridDim.x * blockDim.x;
    float4 z = make_float4(0.f, 0.f, 0.f, 0.f);
    for (; i < n4; i += stride) p[i] = z;
}

__global__ void init_max_k() {
    g_maxs = -INFINITY;
    g_maxd = -INFINITY;
}

// ----------------------------------------------------------------------------
// SGEMM (unchanged from round 3)
// ----------------------------------------------------------------------------
template <int BN, int TN>
__global__ void sgemm(const float* __restrict__ A, const float* __restrict__ B,
                      float* __restrict__ C, int M, int K, int Ncols) {
    const int BM = 128, BK = 8, TM = 8;
    __shared__ alignas(16) float As[BK][BM];
    __shared__ alignas(16) float Bs[BK][BN];

    int tid = threadIdx.x;
    int mBlock = blockIdx.x * BM;
    int nBlock = blockIdx.y * BN;

    const int TCOLS = BN / TN;
    int tcol = tid % TCOLS;
    int trow = tid / TCOLS;

    float acc[TM][TN];
#pragma unroll
    for (int i = 0; i < TM; i++)
#pragma unroll
        for (int j = 0; j < TN; j++) acc[i][j] = 0.f;

    int aRow = tid >> 1;
    int aCol = (tid & 1) * 4;
    int bRow = tid / (BN / 4);
    int bCol = (tid % (BN / 4)) * 4;

    for (int k0 = 0; k0 < K; k0 += BK) {
        float4 av = make_float4(0.f, 0.f, 0.f, 0.f);
        int gr = mBlock + aRow;
        if (gr < M) av = *(const float4*)(A + (size_t)gr * K + k0 + aCol);
        As[aCol + 0][aRow] = av.x;
        As[aCol + 1][aRow] = av.y;
        As[aCol + 2][aRow] = av.z;
        As[aCol + 3][aRow] = av.w;

        if (tid < 2 * BN) {
            float4 bv = *(const float4*)(B + (size_t)(k0 + bRow) * Ncols + nBlock + bCol);
            *(float4*)&Bs[bRow][bCol] = bv;
        }
        __syncthreads();

#pragma unroll
        for (int kk = 0; kk < BK; kk++) {
            float ra[TM], rb[TN];
#pragma unroll
            for (int i = 0; i < TM; i++) ra[i] = As[kk][trow * TM + i];
#pragma unroll
            for (int j = 0; j < TN; j++) rb[j] = Bs[kk][tcol * TN + j];
#pragma unroll
            for (int i = 0; i < TM; i++)
#pragma unroll
                for (int j = 0; j < TN; j++) acc[i][j] += ra[i] * rb[j];
        }
        __syncthreads();
    }

#pragma unroll
    for (int i = 0; i < TM; i++) {
        int row = mBlock + trow * TM + i;
        if (row < M) {
            float* cp = C + (size_t)row * Ncols + nBlock + tcol * TN;
#pragma unroll
            for (int j = 0; j < TN; j++) cp[j] = acc[i][j];
        }
    }
}

// ----------------------------------------------------------------------------
// attn_prep: per (node, head) dot products; zero s; update global maxes
// warp per (node*H + head), 8 warps/block
// ----------------------------------------------------------------------------
template <int H, int C>
__global__ void attn_prep(const float* __restrict__ h,
                          const float* __restrict__ a_src,
                          const float* __restrict__ a_dst,
                          float* __restrict__ als, float* __restrict__ ald,
                          float* __restrict__ s) {
    __shared__ float sm1[8], sm2[8];
    int w = (blockIdx.x * blockDim.x + threadIdx.x) >> 5;
    int lane = threadIdx.x & 31;
    int wib = threadIdx.x >> 5;
    bool valid = (w < NN * H);

    float d1 = 0.f, d2 = 0.f;
    if (valid) {
        int node = w / H;
        int head = w % H;
        const float* hp = h + (size_t)node * (H * C) + head * C;
#pragma unroll
        for (int i = lane; i < C; i += 32) {
            float v = hp[i];
            d1 += v * a_src[head * C + i];
            d2 += v * a_dst[head * C + i];
        }
    }
#pragma unroll
    for (int off = 16; off > 0; off >>= 1) {
        d1 += __shfl_down_sync(0xffffffffu, d1, off);
        d2 += __shfl_down_sync(0xffffffffu, d2, off);
    }
    if (lane == 0) {
        if (valid) {
            als[w] = d1;
            ald[w] = d2;
            s[w]   = 0.f;
            sm1[wib] = d1;
            sm2[wib] = d2;
        } else {
            sm1[wib] = -INFINITY;
            sm2[wib] = -INFINITY;
        }
    }
    __syncthreads();
    if (threadIdx.x == 0) {
        float m1 = sm1[0], m2 = sm2[0];
#pragma unroll
        for (int i = 1; i < 8; i++) {
            m1 = fmaxf(m1, sm1[i]);
            m2 = fmaxf(m2, sm2[i]);
        }
        atomicMaxF(&g_maxs, m1);
        atomicMaxF(&g_maxd, m2);
    }
}

// ----------------------------------------------------------------------------
// Fused edge pass (H=4, C=64): one pass accumulates unnormalized numerator
// (out[dst] += exp(e-Mg) * h[src]) and denominator (s[dst,h] += exp(e-Mg)).
// Warp per edge, 8 floats/lane.
// ----------------------------------------------------------------------------
__global__ void edge_fused4(const int* __restrict__ src, const int* __restrict__ dst,
                            const float* __restrict__ h,
                            const float* __restrict__ als, const float* __restrict__ ald,
                            float* __restrict__ s, float* __restrict__ out) {
    int w = (blockIdx.x * blockDim.x + threadIdx.x) >> 5;
    int lane = threadIdx.x & 31;
    if (w >= NEDGE) return;
    int s0 = src[w], d0 = dst[w];

    float Mg = fmaxf(0.f, g_maxs + g_maxd);
    int head = lane >> 3;                 // 8 lanes per head

    float e  = lrelu(als[s0 * 4 + head] + ald[d0 * 4 + head]);
    float wt = __expf(e - Mg);

    // heads 0..3 live at lanes 0,8,16,24
    float s0v = __shfl_sync(0xffffffffu, wt, 0);
    float s1v = __shfl_sync(0xffffffffu, wt, 8);
    float s2v = __shfl_sync(0xffffffffu, wt, 16);
    float s3v = __shfl_sync(0xffffffffu, wt, 24);
    if (lane == 0)
        atomicAdd((float4*)&s[d0 * 4], make_float4(s0v, s1v, s2v, s3v));

    const float* hp = h + (size_t)s0 * 256 + lane * 8;
    float* op = out + (size_t)d0 * 256 + lane * 8;
#pragma unroll
    for (int i = 0; i < 2; i++) {
        float4 v = *(const float4*)(hp + i * 4);
        atomicAdd((float4*)(op + i * 4),
                  make_float4(v.x * wt, v.y * wt, v.z * wt, v.w * wt));
    }
}

// Fused edge pass (H=1, C=64): 2 floats/lane
__global__ void edge_fused1(const int* __restrict__ src, const int* __restrict__ dst,
                            const float* __restrict__ h,
                            const float* __restrict__ als, const float* __restrict__ ald,
                            float* __restrict__ s, float* __restrict__ out) {
    int w = (blockIdx.x * blockDim.x + threadIdx.x) >> 5;
    int lane = threadIdx.x & 31;
    if (w >= NEDGE) return;
    int s0 = src[w], d0 = dst[w];

    float Mg = fmaxf(0.f, g_maxs + g_maxd);
    float e  = lrelu(als[s0] + ald[d0]);
    float wt = __expf(e - Mg);

    if (lane == 0) atomicAdd(&s[d0], wt);

    const float* hp = h + (size_t)s0 * 64 + lane * 2;
    float* op = out + (size_t)d0 * 64 + lane * 2;
    float2 v = *(const float2*)hp;
    atomicAdd((float2*)op, make_float2(v.x * wt, v.y * wt));
}

// ----------------------------------------------------------------------------
// Normalize: out = [relu]( agg / (s + eps) + bias )   (in place, float4)
// Layers 1,2: H=4, 64 float4 per node. Thread per float4.
// ----------------------------------------------------------------------------
__global__ void normalize4(float4* __restrict__ agg, const float* __restrict__ s,
                           const float4* __restrict__ bias) {
    int i = blockIdx.x * blockDim.x + threadIdx.x;
    if (i >= NN * 64) return;
    int node = i >> 6;
    int head = (i >> 4) & 3;
    float inv = 1.f / (s[node * 4 + head] + EPSV);
    float4 v = agg[i];
    float4 b = bias[i & 63];
    v.x = fmaxf(v.x * inv + b.x, 0.f);
    v.y = fmaxf(v.y * inv + b.y, 0.f);
    v.z = fmaxf(v.z * inv + b.z, 0.f);
    v.w = fmaxf(v.w * inv + b.w, 0.f);
    agg[i] = v;
}

// Layer 3: H=1, 16 float4 per node, no bias/relu (b3 folded into final_k)
__global__ void normalize1(float4* __restrict__ agg, const float* __restrict__ s) {
    int i = blockIdx.x * blockDim.x + threadIdx.x;
    if (i >= NN * 16) return;
    int node = i >> 4;
    float inv = 1.f / (s[node] + EPSV);
    float4 v = agg[i];
    v.x *= inv; v.y *= inv; v.z *= inv; v.w *= inv;
    agg[i] = v;
}

// ----------------------------------------------------------------------------
// Per-graph counts (binary search on sorted batch)
// ----------------------------------------------------------------------------
__global__ void counts_k(const int* __restrict__ batch, float* __restrict__ cnt) {
    int g = threadIdx.x;
    if (g >= NGRAPH) return;
    int lo = 0, hi = NN;
    while (lo < hi) { int mid = (lo + hi) >> 1; if (batch[mid] < g) lo = mid + 1; else hi = mid; }
    int a = lo;
    lo = 0; hi = NN;
    while (lo < hi) { int mid = (lo + hi) >> 1; if (batch[mid] < g + 1) lo = mid + 1; else hi = mid; }
    cnt[g] = (float)(lo - a);
}

__global__ void pool_sum(const float* __restrict__ h, const int* __restrict__ batch,
                         float* __restrict__ pool) {
    int c = threadIdx.x & 63;
    int r = threadIdx.x >> 6;
    int start = blockIdx.x * 1024;
    int end = start + 1024;
    if (end > NN) end = NN;
    int cur = -1;
    float acc = 0.f;
    for (int nd = start + r; nd < end; nd += 4) {
        int g = batch[nd];
        if (g != cur) {
            if (cur >= 0) atomicAdd(&pool[cur * 64 + c], acc);
            cur = g;
            acc = 0.f;
        }
        acc += h[(size_t)nd * 64 + c];
    }
    if (cur >= 0) atomicAdd(&pool[cur * 64 + c], acc);
}

__global__ void final_k(const float* __restrict__ pool, const float* __restrict__ cnt,
                        const float* __restrict__ b3,
                        const float* __restrict__ linW, const float* __restrict__ linb,
                        float* __restrict__ out) {
    int g = blockIdx.x;
    int j = threadIdx.x;
    __shared__ float mean[64];
    float cc = fmaxf(cnt[g], 1.f);
    mean[j] = pool[g * 64 + j] / cc + b3[j];
    __syncthreads();
    float acc = 0.f;
#pragma unroll
    for (int k = 0; k < 64; k++) acc += mean[k] * linW[k * 64 + j];
    out[g * 64 + j] = acc + linb[j];
}

// ----------------------------------------------------------------------------
// Host launcher
// ----------------------------------------------------------------------------
extern "C" void kernel_launch(void* const* d_in, const int* in_sizes, int n_in,
                              void* d_out, int out_size) {
    const float* x     = (const float*)d_in[0];
    const void*  ei    = d_in[1];
    const void*  batch = d_in[3];
    const float* W1  = (const float*)d_in[4];
    const float* a1s = (const float*)d_in[5];
    const float* a1d = (const float*)d_in[6];
    const float* b1  = (const float*)d_in[7];
    const float* W2  = (const float*)d_in[8];
    const float* a2s = (const float*)d_in[9];
    const float* a2d = (const float*)d_in[10];
    const float* b2  = (const float*)d_in[11];
    const float* W3  = (const float*)d_in[12];
    const float* a3s = (const float*)d_in[13];
    const float* a3d = (const float*)d_in[14];
    const float* b3  = (const float*)d_in[15];
    const float* lW  = (const float*)d_in[16];
    const float* lb  = (const float*)d_in[17];
    float* out = (float*)d_out;

    float *p_h, *p_agg, *p_als, *p_ald, *p_s, *p_pool, *p_cnt;
    int *p_src, *p_dst, *p_batch;
    cudaGetSymbolAddress((void**)&p_h,    g_h);
    cudaGetSymbolAddress((void**)&p_agg,  g_agg);
    cudaGetSymbolAddress((void**)&p_als,  g_als);
    cudaGetSymbolAddress((void**)&p_ald,  g_ald);
    cudaGetSymbolAddress((void**)&p_s,    g_s);
    cudaGetSymbolAddress((void**)&p_src,  g_src);
    cudaGetSymbolAddress((void**)&p_dst,  g_dst);
    cudaGetSymbolAddress((void**)&p_batch,g_batch);
    cudaGetSymbolAddress((void**)&p_pool, g_pool);
    cudaGetSymbolAddress((void**)&p_cnt,  g_cnt);

    const int TB = 256;
    const int edgeWarpBlocks = (NEDGE * 32 + TB - 1) / TB;
    const int mTiles = (NN + 127) / 128;

    detect_dtype<<<1, 32>>>((const unsigned int*)ei);
    conv_edges<<<(NEDGE + TB - 1) / TB, TB>>>(ei, p_src, p_dst);
    conv_batch<<<(NN + TB - 1) / TB, TB>>>(batch, p_batch);

    // ================= Layer 1: 128 -> 4x64 =================
    {
        dim3 grid(mTiles, HC12 / 128);
        sgemm<128, 8><<<grid, TB>>>(x, W1, p_h, NN, 128, HC12);
        init_max_k<<<1, 1>>>();
        attn_prep<4, 64><<<(NN * 4 * 32 + TB - 1) / TB, TB>>>(p_h, a1s, a1d, p_als, p_ald, p_s);
        zero_f4<<<4096, TB>>>((float4*)p_agg, NN * HC12 / 4);
        edge_fused4<<<edgeWarpBlocks, TB>>>(p_src, p_dst, p_h, p_als, p_ald, p_s, p_agg);
        normalize4<<<(NN * 64 + TB - 1) / TB, TB>>>((float4*)p_agg, p_s, (const float4*)b1);
    }

    // ================= Layer 2: 256 -> 4x64 =================
    {
        dim3 grid(mTiles, HC12 / 128);
        sgemm<128, 8><<<grid, TB>>>(p_agg, W2, p_h, NN, HC12, HC12);
        init_max_k<<<1, 1>>>();
        attn_prep<4, 64><<<(NN * 4 * 32 + TB - 1) / TB, TB>>>(p_h, a2s, a2d, p_als, p_ald, p_s);
        zero_f4<<<4096, TB>>>((float4*)p_agg, NN * HC12 / 4);
        edge_fused4<<<edgeWarpBlocks, TB>>>(p_src, p_dst, p_h, p_als, p_ald, p_s, p_agg);
        normalize4<<<(NN * 64 + TB - 1) / TB, TB>>>((float4*)p_agg, p_s, (const float4*)b2);
    }

    // ================= Layer 3: 256 -> 1x64 =================
    {
        dim3 grid(mTiles, 1);
        sgemm<64, 4><<<grid, TB>>>(p_agg, W3, p_h, NN, HC12, HC3);
        init_max_k<<<1, 1>>>();
        attn_prep<1, 64><<<(NN * 32 + TB - 1) / TB, TB>>>(p_h, a3s, a3d, p_als, p_ald, p_s);
        zero_f4<<<2048, TB>>>((float4*)p_agg, NN * HC3 / 4);
        edge_fused1<<<edgeWarpBlocks, TB>>>(p_src, p_dst, p_h, p_als, p_ald, p_s, p_agg);
        normalize1<<<(NN * 16 + TB - 1) / TB, TB>>>((float4*)p_agg, p_s);
    }

    // ================= Pool + final linear =================
    zero_f4<<<4, 64>>>((float4*)p_pool, NGRAPH * HC3 / 4);
    zero_f4<<<1, 64>>>((float4*)p_cnt, NGRAPH / 4);
    counts_k<<<1, 64>>>(p_batch, p_cnt);
    pool_sum<<<(NN + 1023) / 1024, 256>>>(p_agg, p_batch, p_pool);
    final_k<<<NGRAPH, 64>>>(p_pool, p_cnt, b3, lW, lb, out);
}

// round 5
// speedup vs baseline: 1.8158x; 1.6223x over previous
#include <cuda_runtime.h>
#include <cuda_bf16.h>
#include <math.h>

// ----------------------------------------------------------------------------
// Problem constants
// ----------------------------------------------------------------------------
#define NN      50000
#define EE      800000
#define NEDGE   (EE + NN)       // with self loops = 850000
#define NGRAPH  64
#define HC12    256
#define HC3     64
#define NEG_SLOPE 0.2f
#define EPSV    1e-16f

// ----------------------------------------------------------------------------
// Device scratch
// ----------------------------------------------------------------------------
__device__ __align__(256) float g_h   [(size_t)NN * HC12];
__device__ __align__(256) float g_agg [(size_t)NN * HC12];
__device__ __align__(256) float g_als [NN * 4];
__device__ __align__(256) float g_ald [NN * 4];
__device__ __align__(256) int   g_src [NEDGE];
__device__ __align__(256) int   g_dst [NEDGE];
__device__ __align__(256) int   g_off [NN + 1];   // CSR offsets (by dst)
__device__ __align__(256) int   g_cur [NN];       // scatter cursors
__device__ __align__(256) int   g_csr [NEDGE];    // src ids sorted by dst
__device__ __align__(256) int   g_batch[NN];
__device__ __align__(256) float g_pool[NGRAPH * HC3];
__device__ __align__(256) float g_cnt [NGRAPH];
__device__ int   g_is64;
__device__ float g_maxs;
__device__ float g_maxd;

// ----------------------------------------------------------------------------
// Helpers
// ----------------------------------------------------------------------------
__device__ __forceinline__ float lrelu(float x) {
    return x >= 0.f ? x : NEG_SLOPE * x;
}
__device__ __forceinline__ void atomicMaxF(float* addr, float v) {
    if (v >= 0.f) atomicMax((int*)addr, __float_as_int(v));
    else          atomicMin((unsigned int*)addr, __float_as_uint(v));
}

// ----------------------------------------------------------------------------
// Dtype probe (int32 vs int64 indices)
// ----------------------------------------------------------------------------
__global__ void detect_dtype(const unsigned int* __restrict__ w) {
    if (threadIdx.x == 0 && blockIdx.x == 0) {
        int all0 = 1;
        for (int i = 1; i < 128; i += 2)
            if (w[i] != 0u) { all0 = 0; break; }
        g_is64 = all0;
    }
}

__global__ void zero_i(int* __restrict__ p, int n) {
    int i = blockIdx.x * blockDim.x + threadIdx.x;
    if (i < n) p[i] = 0;
}

// conv + histogram (counts land at off[d+1])
__global__ void conv_edges(const void* __restrict__ ei_raw,
                           int* __restrict__ src, int* __restrict__ dst,
                           int* __restrict__ off) {
    int i = blockIdx.x * blockDim.x + threadIdx.x;
    if (i >= NEDGE) return;
    int sv, dv;
    if (i >= EE) {
        sv = dv = i - EE;
    } else if (g_is64) {
        const long long* e = (const long long*)ei_raw;
        sv = (int)e[i];
        dv = (int)e[EE + i];
    } else {
        const int* e = (const int*)ei_raw;
        sv = e[i];
        dv = e[EE + i];
    }
    src[i] = sv;
    dst[i] = dv;
    atomicAdd(&off[dv + 1], 1);
}

__global__ void conv_batch(const void* __restrict__ b_raw, int* __restrict__ bo) {
    int i = blockIdx.x * blockDim.x + threadIdx.x;
    if (i >= NN) return;
    bo[i] = g_is64 ? (int)((const long long*)b_raw)[i] : ((const int*)b_raw)[i];
}

// single-block inclusive scan over n ints (n = NN+1)
__global__ void scan_k(int* __restrict__ a, int n) {
    __shared__ int warp_sums[32];
    __shared__ int carry_s;
    int tid = threadIdx.x, lane = tid & 31, wid = tid >> 5;
    if (tid == 0) carry_s = 0;
    __syncthreads();
    for (int base = 0; base < n; base += 1024) {
        int idx = base + tid;
        int v = (idx < n) ? a[idx] : 0;
#pragma unroll
        for (int off = 1; off < 32; off <<= 1) {
            int t = __shfl_up_sync(0xffffffffu, v, off);
            if (lane >= off) v += t;
        }
        if (lane == 31) warp_sums[wid] = v;
        __syncthreads();
        if (wid == 0) {
            int w = warp_sums[lane];
#pragma unroll
            for (int off = 1; off < 32; off <<= 1) {
                int t = __shfl_up_sync(0xffffffffu, w, off);
                if (lane >= off) w += t;
            }
            warp_sums[lane] = w;
        }
        __syncthreads();
        int add = (wid > 0 ? warp_sums[wid - 1] : 0) + carry_s;
        if (idx < n) a[idx] = v + add;
        int total = warp_sums[31];
        __syncthreads();
        if (tid == 0) carry_s += total;
        __syncthreads();
    }
}

__global__ void set_cursors(const int* __restrict__ off, int* __restrict__ cur) {
    int i = blockIdx.x * blockDim.x + threadIdx.x;
    if (i < NN) cur[i] = off[i];
}

__global__ void scatter_csr(const int* __restrict__ src, const int* __restrict__ dst,
                            int* __restrict__ cur, int* __restrict__ csr) {
    int i = blockIdx.x * blockDim.x + threadIdx.x;
    if (i >= NEDGE) return;
    int pos = atomicAdd(&cur[dst[i]], 1);
    csr[pos] = src[i];
}

__global__ void init_max_k() {
    g_maxs = -INFINITY;
    g_maxd = -INFINITY;
}

// ----------------------------------------------------------------------------
// SGEMM (unchanged)
// ----------------------------------------------------------------------------
template <int BN, int TN>
__global__ void sgemm(const float* __restrict__ A, const float* __restrict__ B,
                      float* __restrict__ C, int M, int K, int Ncols) {
    const int BM = 128, BK = 8, TM = 8;
    __shared__ alignas(16) float As[BK][BM];
    __shared__ alignas(16) float Bs[BK][BN];

    int tid = threadIdx.x;
    int mBlock = blockIdx.x * BM;
    int nBlock = blockIdx.y * BN;

    const int TCOLS = BN / TN;
    int tcol = tid % TCOLS;
    int trow = tid / TCOLS;

    float acc[TM][TN];
#pragma unroll
    for (int i = 0; i < TM; i++)
#pragma unroll
        for (int j = 0; j < TN; j++) acc[i][j] = 0.f;

    int aRow = tid >> 1;
    int aCol = (tid & 1) * 4;
    int bRow = tid / (BN / 4);
    int bCol = (tid % (BN / 4)) * 4;

    for (int k0 = 0; k0 < K; k0 += BK) {
        float4 av = make_float4(0.f, 0.f, 0.f, 0.f);
        int gr = mBlock + aRow;
        if (gr < M) av = *(const float4*)(A + (size_t)gr * K + k0 + aCol);
        As[aCol + 0][aRow] = av.x;
        As[aCol + 1][aRow] = av.y;
        As[aCol + 2][aRow] = av.z;
        As[aCol + 3][aRow] = av.w;

        if (tid < 2 * BN) {
            float4 bv = *(const float4*)(B + (size_t)(k0 + bRow) * Ncols + nBlock + bCol);
            *(float4*)&Bs[bRow][bCol] = bv;
        }
        __syncthreads();

#pragma unroll
        for (int kk = 0; kk < BK; kk++) {
            float ra[TM], rb[TN];
#pragma unroll
            for (int i = 0; i < TM; i++) ra[i] = As[kk][trow * TM + i];
#pragma unroll
            for (int j = 0; j < TN; j++) rb[j] = Bs[kk][tcol * TN + j];
#pragma unroll
            for (int i = 0; i < TM; i++)
#pragma unroll
                for (int j = 0; j < TN; j++) acc[i][j] += ra[i] * rb[j];
        }
        __syncthreads();
    }

#pragma unroll
    for (int i = 0; i < TM; i++) {
        int row = mBlock + trow * TM + i;
        if (row < M) {
            float* cp = C + (size_t)row * Ncols + nBlock + tcol * TN;
#pragma unroll
            for (int j = 0; j < TN; j++) cp[j] = acc[i][j];
        }
    }
}

// ----------------------------------------------------------------------------
// attn_prep: per (node, head) dot products + global maxes
// ----------------------------------------------------------------------------
template <int H, int C>
__global__ void attn_prep(const float* __restrict__ h,
                          const float* __restrict__ a_src,
                          const float* __restrict__ a_dst,
                          float* __restrict__ als, float* __restrict__ ald) {
    __shared__ float sm1[8], sm2[8];
    int w = (blockIdx.x * blockDim.x + threadIdx.x) >> 5;
    int lane = threadIdx.x & 31;
    int wib = threadIdx.x >> 5;
    bool valid = (w < NN * H);

    float d1 = 0.f, d2 = 0.f;
    if (valid) {
        int node = w / H;
        int head = w % H;
        const float* hp = h + (size_t)node * (H * C) + head * C;
#pragma unroll
        for (int i = lane; i < C; i += 32) {
            float v = hp[i];
            d1 += v * a_src[head * C + i];
            d2 += v * a_dst[head * C + i];
        }
    }
#pragma unroll
    for (int off = 16; off > 0; off >>= 1) {
        d1 += __shfl_down_sync(0xffffffffu, d1, off);
        d2 += __shfl_down_sync(0xffffffffu, d2, off);
    }
    if (lane == 0) {
        if (valid) {
            als[w] = d1;
            ald[w] = d2;
            sm1[wib] = d1;
            sm2[wib] = d2;
        } else {
            sm1[wib] = -INFINITY;
            sm2[wib] = -INFINITY;
        }
    }
    __syncthreads();
    if (threadIdx.x == 0) {
        float m1 = sm1[0], m2 = sm2[0];
#pragma unroll
        for (int i = 1; i < 8; i++) {
            m1 = fmaxf(m1, sm1[i]);
            m2 = fmaxf(m2, sm2[i]);
        }
        atomicMaxF(&g_maxs, m1);
        atomicMaxF(&g_maxd, m2);
    }
}

// ----------------------------------------------------------------------------
// CSR gather-aggregate, H=4 C=64. Warp per dst node; 8 floats/lane.
// Numerator + denominator in registers; normalize+bias+relu fused; single store.
// ----------------------------------------------------------------------------
__global__ void gat_agg4(const int* __restrict__ off, const int* __restrict__ csr,
                         const float* __restrict__ h,
                         const float* __restrict__ als, const float* __restrict__ ald,
                         const float4* __restrict__ bias, float* __restrict__ out) {
    int node = (blockIdx.x * blockDim.x + threadIdx.x) >> 5;
    int lane = threadIdx.x & 31;
    if (node >= NN) return;

    float Mg = fmaxf(0.f, g_maxs + g_maxd);
    int head = lane >> 3;             // 8 lanes per head
    float aldv = ald[node * 4 + head];

    float4 acc0 = make_float4(0.f, 0.f, 0.f, 0.f);
    float4 acc1 = make_float4(0.f, 0.f, 0.f, 0.f);
    float ssum = 0.f;

    int beg = off[node], end = off[node + 1];
    int i = beg;
    for (; i + 1 < end; i += 2) {
        int s0 = csr[i], s1 = csr[i + 1];
        float wt0 = __expf(lrelu(als[s0 * 4 + head] + aldv) - Mg);
        float wt1 = __expf(lrelu(als[s1 * 4 + head] + aldv) - Mg);
        const float4* h0 = (const float4*)(h + (size_t)s0 * 256 + lane * 8);
        const float4* h1 = (const float4*)(h + (size_t)s1 * 256 + lane * 8);
        float4 v00 = h0[0], v01 = h0[1];
        float4 v10 = h1[0], v11 = h1[1];
        ssum += wt0 + wt1;
        acc0.x += wt0 * v00.x + wt1 * v10.x;
        acc0.y += wt0 * v00.y + wt1 * v10.y;
        acc0.z += wt0 * v00.z + wt1 * v10.z;
        acc0.w += wt0 * v00.w + wt1 * v10.w;
        acc1.x += wt0 * v01.x + wt1 * v11.x;
        acc1.y += wt0 * v01.y + wt1 * v11.y;
        acc1.z += wt0 * v01.z + wt1 * v11.z;
        acc1.w += wt0 * v01.w + wt1 * v11.w;
    }
    if (i < end) {
        int s0 = csr[i];
        float wt0 = __expf(lrelu(als[s0 * 4 + head] + aldv) - Mg);
        const float4* h0 = (const float4*)(h + (size_t)s0 * 256 + lane * 8);
        float4 v00 = h0[0], v01 = h0[1];
        ssum += wt0;
        acc0.x += wt0 * v00.x; acc0.y += wt0 * v00.y;
        acc0.z += wt0 * v00.z; acc0.w += wt0 * v00.w;
        acc1.x += wt0 * v01.x; acc1.y += wt0 * v01.y;
        acc1.z += wt0 * v01.z; acc1.w += wt0 * v01.w;
    }

    float inv = 1.f / (ssum + EPSV);
    float4 b0 = bias[lane * 2];
    float4 b1 = bias[lane * 2 + 1];
    float4 r0, r1;
    r0.x = fmaxf(acc0.x * inv + b0.x, 0.f);
    r0.y = fmaxf(acc0.y * inv + b0.y, 0.f);
    r0.z = fmaxf(acc0.z * inv + b0.z, 0.f);
    r0.w = fmaxf(acc0.w * inv + b0.w, 0.f);
    r1.x = fmaxf(acc1.x * inv + b1.x, 0.f);
    r1.y = fmaxf(acc1.y * inv + b1.y, 0.f);
    r1.z = fmaxf(acc1.z * inv + b1.z, 0.f);
    r1.w = fmaxf(acc1.w * inv + b1.w, 0.f);
    float4* op = (float4*)(out + (size_t)node * 256 + lane * 8);
    op[0] = r0;
    op[1] = r1;
}

// CSR gather-aggregate, H=1 C=64. Warp per node, 2 floats/lane. No bias/relu.
__global__ void gat_agg1(const int* __restrict__ off, const int* __restrict__ csr,
                         const float* __restrict__ h,
                         const float* __restrict__ als, const float* __restrict__ ald,
                         float* __restrict__ out) {
    int node = (blockIdx.x * blockDim.x + threadIdx.x) >> 5;
    int lane = threadIdx.x & 31;
    if (node >= NN) return;

    float Mg = fmaxf(0.f, g_maxs + g_maxd);
    float aldv = ald[node];

    float2 acc = make_float2(0.f, 0.f);
    float ssum = 0.f;

    int beg = off[node], end = off[node + 1];
    int i = beg;
    for (; i + 1 < end; i += 2) {
        int s0 = csr[i], s1 = csr[i + 1];
        float wt0 = __expf(lrelu(als[s0] + aldv) - Mg);
        float wt1 = __expf(lrelu(als[s1] + aldv) - Mg);
        float2 v0 = *(const float2*)(h + (size_t)s0 * 64 + lane * 2);
        float2 v1 = *(const float2*)(h + (size_t)s1 * 64 + lane * 2);
        ssum += wt0 + wt1;
        acc.x += wt0 * v0.x + wt1 * v1.x;
        acc.y += wt0 * v0.y + wt1 * v1.y;
    }
    if (i < end) {
        int s0 = csr[i];
        float wt0 = __expf(lrelu(als[s0] + aldv) - Mg);
        float2 v0 = *(const float2*)(h + (size_t)s0 * 64 + lane * 2);
        ssum += wt0;
        acc.x += wt0 * v0.x;
        acc.y += wt0 * v0.y;
    }

    float inv = 1.f / (ssum + EPSV);
    *(float2*)(out + (size_t)node * 64 + lane * 2) =
        make_float2(acc.x * inv, acc.y * inv);
}

// ----------------------------------------------------------------------------
// Pool + final
// ----------------------------------------------------------------------------
__global__ void zero_f4(float4* __restrict__ p, int n4) {
    int i = blockIdx.x * blockDim.x + threadIdx.x;
    int stride = gridDim.x * blockDim.x;
    float4 z = make_float4(0.f, 0.f, 0.f, 0.f);
    for (; i < n4; i += stride) p[i] = z;
}

__global__ void counts_k(const int* __restrict__ batch, float* __restrict__ cnt) {
    int g = threadIdx.x;
    if (g >= NGRAPH) return;
    int lo = 0, hi = NN;
    while (lo < hi) { int mid = (lo + hi) >> 1; if (batch[mid] < g) lo = mid + 1; else hi = mid; }
    int a = lo;
    lo = 0; hi = NN;
    while (lo < hi) { int mid = (lo + hi) >> 1; if (batch[mid] < g + 1) lo = mid + 1; else hi = mid; }
    cnt[g] = (float)(lo - a);
}

__global__ void pool_sum(const float* __restrict__ h, const int* __restrict__ batch,
                         float* __restrict__ pool) {
    int c = threadIdx.x & 63;
    int r = threadIdx.x >> 6;
    int start = blockIdx.x * 1024;
    int end = start + 1024;
    if (end > NN) end = NN;
    int cur = -1;
    float acc = 0.f;
    for (int nd = start + r; nd < end; nd += 4) {
        int g = batch[nd];
        if (g != cur) {
            if (cur >= 0) atomicAdd(&pool[cur * 64 + c], acc);
            cur = g;
            acc = 0.f;
        }
        acc += h[(size_t)nd * 64 + c];
    }
    if (cur >= 0) atomicAdd(&pool[cur * 64 + c], acc);
}

__global__ void final_k(const float* __restrict__ pool, const float* __restrict__ cnt,
                        const float* __restrict__ b3,
                        const float* __restrict__ linW, const float* __restrict__ linb,
                        float* __restrict__ out) {
    int g = blockIdx.x;
    int j = threadIdx.x;
    __shared__ float mean[64];
    float cc = fmaxf(cnt[g], 1.f);
    mean[j] = pool[g * 64 + j] / cc + b3[j];
    __syncthreads();
    float acc = 0.f;
#pragma unroll
    for (int k = 0; k < 64; k++) acc += mean[k] * linW[k * 64 + j];
    out[g * 64 + j] = acc + linb[j];
}

// ----------------------------------------------------------------------------
// Host launcher
// ----------------------------------------------------------------------------
extern "C" void kernel_launch(void* const* d_in, const int* in_sizes, int n_in,
                              void* d_out, int out_size) {
    const float* x     = (const float*)d_in[0];
    const void*  ei    = d_in[1];
    const void*  batch = d_in[3];
    const float* W1  = (const float*)d_in[4];
    const float* a1s = (const float*)d_in[5];
    const float* a1d = (const float*)d_in[6];
    const float* b1  = (const float*)d_in[7];
    const float* W2  = (const float*)d_in[8];
    const float* a2s = (const float*)d_in[9];
    const float* a2d = (const float*)d_in[10];
    const float* b2  = (const float*)d_in[11];
    const float* W3  = (const float*)d_in[12];
    const float* a3s = (const float*)d_in[13];
    const float* a3d = (const float*)d_in[14];
    const float* b3  = (const float*)d_in[15];
    const float* lW  = (const float*)d_in[16];
    const float* lb  = (const float*)d_in[17];
    float* out = (float*)d_out;

    float *p_h, *p_agg, *p_als, *p_ald, *p_pool, *p_cnt;
    int *p_src, *p_dst, *p_off, *p_cur, *p_csr, *p_batch;
    cudaGetSymbolAddress((void**)&p_h,    g_h);
    cudaGetSymbolAddress((void**)&p_agg,  g_agg);
    cudaGetSymbolAddress((void**)&p_als,  g_als);
    cudaGetSymbolAddress((void**)&p_ald,  g_ald);
    cudaGetSymbolAddress((void**)&p_src,  g_src);
    cudaGetSymbolAddress((void**)&p_dst,  g_dst);
    cudaGetSymbolAddress((void**)&p_off,  g_off);
    cudaGetSymbolAddress((void**)&p_cur,  g_cur);
    cudaGetSymbolAddress((void**)&p_csr,  g_csr);
    cudaGetSymbolAddress((void**)&p_batch,g_batch);
    cudaGetSymbolAddress((void**)&p_pool, g_pool);
    cudaGetSymbolAddress((void**)&p_cnt,  g_cnt);

    const int TB = 256;
    const int mTiles = (NN + 127) / 128;
    const int nodeWarpBlocks = (NN * 32 + TB - 1) / TB;

    // --- CSR build (once; reused across all 3 layers) ---
    detect_dtype<<<1, 32>>>((const unsigned int*)ei);
    zero_i<<<(NN + 1 + TB - 1) / TB, TB>>>(p_off, NN + 1);
    conv_edges<<<(NEDGE + TB - 1) / TB, TB>>>(ei, p_src, p_dst, p_off);
    conv_batch<<<(NN + TB - 1) / TB, TB>>>(batch, p_batch);
    scan_k<<<1, 1024>>>(p_off, NN + 1);
    set_cursors<<<(NN + TB - 1) / TB, TB>>>(p_off, p_cur);
    scatter_csr<<<(NEDGE + TB - 1) / TB, TB>>>(p_src, p_dst, p_cur, p_csr);

    // ================= Layer 1: 128 -> 4x64 =================
    {
        dim3 grid(mTiles, HC12 / 128);
        sgemm<128, 8><<<grid, TB>>>(x, W1, p_h, NN, 128, HC12);
        init_max_k<<<1, 1>>>();
        attn_prep<4, 64><<<(NN * 4 * 32 + TB - 1) / TB, TB>>>(p_h, a1s, a1d, p_als, p_ald);
        gat_agg4<<<nodeWarpBlocks, TB>>>(p_off, p_csr, p_h, p_als, p_ald, (const float4*)b1, p_agg);
    }

    // ================= Layer 2: 256 -> 4x64 =================
    {
        dim3 grid(mTiles, HC12 / 128);
        sgemm<128, 8><<<grid, TB>>>(p_agg, W2, p_h, NN, HC12, HC12);
        init_max_k<<<1, 1>>>();
        attn_prep<4, 64><<<(NN * 4 * 32 + TB - 1) / TB, TB>>>(p_h, a2s, a2d, p_als, p_ald);
        gat_agg4<<<nodeWarpBlocks, TB>>>(p_off, p_csr, p_h, p_als, p_ald, (const float4*)b2, p_agg);
    }

    // ================= Layer 3: 256 -> 1x64 =================
    {
        dim3 grid(mTiles, 1);
        sgemm<64, 4><<<grid, TB>>>(p_agg, W3, p_h, NN, HC12, HC3);
        init_max_k<<<1, 1>>>();
        attn_prep<1, 64><<<(NN * 32 + TB - 1) / TB, TB>>>(p_h, a3s, a3d, p_als, p_ald);
        gat_agg1<<<nodeWarpBlocks, TB>>>(p_off, p_csr, p_h, p_als, p_ald, p_agg);
    }

    // ================= Pool + final linear =================
    zero_f4<<<4, 64>>>((float4*)p_pool, NGRAPH * HC3 / 4);
    counts_k<<<1, 64>>>(p_batch, p_cnt);
    pool_sum<<<(NN + 1023) / 1024, 256>>>(p_agg, p_batch, p_pool);
    final_k<<<NGRAPH, 64>>>(p_pool, p_cnt, b3, lW, lb, out);
}

// round 6
// speedup vs baseline: 1.9718x; 1.0859x over previous
#include <cuda_runtime.h>
#include <cuda_bf16.h>
#include <math.h>

// ----------------------------------------------------------------------------
// Problem constants
// ----------------------------------------------------------------------------
#define NN      50000
#define EE      800000
#define NEDGE   (EE + NN)       // with self loops = 850000
#define NGRAPH  64
#define HC12    256
#define HC3     64
#define NEG_SLOPE 0.2f
#define EPSV    1e-16f

// ----------------------------------------------------------------------------
// Device scratch
// ----------------------------------------------------------------------------
__device__ __align__(256) float g_h   [(size_t)NN * HC12];
__device__ __align__(256) float g_agg [(size_t)NN * HC12];
__device__ __align__(256) float g_als [NN * 4];
__device__ __align__(256) float g_ald [NN * 4];
__device__ __align__(256) int   g_src [NEDGE];
__device__ __align__(256) int   g_dst [NEDGE];
__device__ __align__(256) int   g_off [NN + 1];
__device__ __align__(256) int   g_cur [NN];
__device__ __align__(256) int   g_csr [NEDGE];
__device__ __align__(256) int   g_batch[NN];
__device__ __align__(256) float g_pool[NGRAPH * HC3];
__device__ __align__(256) float g_cnt [NGRAPH];
__device__ int   g_is64;
__device__ float g_maxs;
__device__ float g_maxd;

// ----------------------------------------------------------------------------
// Helpers
// ----------------------------------------------------------------------------
__device__ __forceinline__ float lrelu(float x) {
    return x >= 0.f ? x : NEG_SLOPE * x;
}
__device__ __forceinline__ void atomicMaxF(float* addr, float v) {
    if (v >= 0.f) atomicMax((int*)addr, __float_as_int(v));
    else          atomicMin((unsigned int*)addr, __float_as_uint(v));
}

// ----------------------------------------------------------------------------
// Dtype probe + CSR build
// ----------------------------------------------------------------------------
__global__ void detect_dtype(const unsigned int* __restrict__ w) {
    if (threadIdx.x == 0 && blockIdx.x == 0) {
        int all0 = 1;
        for (int i = 1; i < 128; i += 2)
            if (w[i] != 0u) { all0 = 0; break; }
        g_is64 = all0;
    }
}

__global__ void zero_i(int* __restrict__ p, int n) {
    int i = blockIdx.x * blockDim.x + threadIdx.x;
    if (i < n) p[i] = 0;
}

__global__ void conv_edges(const void* __restrict__ ei_raw,
                           int* __restrict__ src, int* __restrict__ dst,
                           int* __restrict__ off) {
    int i = blockIdx.x * blockDim.x + threadIdx.x;
    if (i >= NEDGE) return;
    int sv, dv;
    if (i >= EE) {
        sv = dv = i - EE;
    } else if (g_is64) {
        const long long* e = (const long long*)ei_raw;
        sv = (int)e[i];
        dv = (int)e[EE + i];
    } else {
        const int* e = (const int*)ei_raw;
        sv = e[i];
        dv = e[EE + i];
    }
    src[i] = sv;
    dst[i] = dv;
    atomicAdd(&off[dv + 1], 1);
}

__global__ void conv_batch(const void* __restrict__ b_raw, int* __restrict__ bo) {
    int i = blockIdx.x * blockDim.x + threadIdx.x;
    if (i >= NN) return;
    bo[i] = g_is64 ? (int)((const long long*)b_raw)[i] : ((const int*)b_raw)[i];
}

__global__ void scan_k(int* __restrict__ a, int n) {
    __shared__ int warp_sums[32];
    __shared__ int carry_s;
    int tid = threadIdx.x, lane = tid & 31, wid = tid >> 5;
    if (tid == 0) carry_s = 0;
    __syncthreads();
    for (int base = 0; base < n; base += 1024) {
        int idx = base + tid;
        int v = (idx < n) ? a[idx] : 0;
#pragma unroll
        for (int off = 1; off < 32; off <<= 1) {
            int t = __shfl_up_sync(0xffffffffu, v, off);
            if (lane >= off) v += t;
        }
        if (lane == 31) warp_sums[wid] = v;
        __syncthreads();
        if (wid == 0) {
            int w = warp_sums[lane];
#pragma unroll
            for (int off = 1; off < 32; off <<= 1) {
                int t = __shfl_up_sync(0xffffffffu, w, off);
                if (lane >= off) w += t;
            }
            warp_sums[lane] = w;
        }
        __syncthreads();
        int add = (wid > 0 ? warp_sums[wid - 1] : 0) + carry_s;
        if (idx < n) a[idx] = v + add;
        int total = warp_sums[31];
        __syncthreads();
        if (tid == 0) carry_s += total;
        __syncthreads();
    }
}

__global__ void set_cursors(const int* __restrict__ off, int* __restrict__ cur) {
    int i = blockIdx.x * blockDim.x + threadIdx.x;
    if (i < NN) cur[i] = off[i];
}

__global__ void scatter_csr(const int* __restrict__ src, const int* __restrict__ dst,
                            int* __restrict__ cur, int* __restrict__ csr) {
    int i = blockIdx.x * blockDim.x + threadIdx.x;
    if (i >= NEDGE) return;
    int pos = atomicAdd(&cur[dst[i]], 1);
    csr[pos] = src[i];
}

__global__ void init_max_k() {
    g_maxs = -INFINITY;
    g_maxd = -INFINITY;
}

// ----------------------------------------------------------------------------
// Global max of als/ald (tiny)
// ----------------------------------------------------------------------------
__global__ void max_reduce(const float* __restrict__ als, const float* __restrict__ ald,
                           int n) {
    __shared__ float sm1[8], sm2[8];
    int lane = threadIdx.x & 31, wib = threadIdx.x >> 5;
    float m1 = -INFINITY, m2 = -INFINITY;
    for (int i = blockIdx.x * blockDim.x + threadIdx.x; i < n;
         i += gridDim.x * blockDim.x) {
        m1 = fmaxf(m1, als[i]);
        m2 = fmaxf(m2, ald[i]);
    }
#pragma unroll
    for (int off = 16; off > 0; off >>= 1) {
        m1 = fmaxf(m1, __shfl_down_sync(0xffffffffu, m1, off));
        m2 = fmaxf(m2, __shfl_down_sync(0xffffffffu, m2, off));
    }
    if (lane == 0) { sm1[wib] = m1; sm2[wib] = m2; }
    __syncthreads();
    if (threadIdx.x == 0) {
        for (int i = 1; i < (int)(blockDim.x >> 5); i++) {
            m1 = fmaxf(m1, sm1[i]);
            m2 = fmaxf(m2, sm2[i]);
        }
        atomicMaxF(&g_maxs, sm1[0] > m1 ? sm1[0] : m1);
        atomicMaxF(&g_maxd, sm2[0] > m2 ? sm2[0] : m2);
    }
}

// ----------------------------------------------------------------------------
// Double-buffered SGEMM with fused attention-dot epilogue.
// C[M,Ncols] = A[M,K] @ B[K,Ncols];  als/ald[row*H+head] = dot(C row slice, a_vec)
// BM=128, BK=8, TM=8. BN/TN/H templated. 256 threads, 2 CTAs/SM.
// Heads are 64-column aligned and BN covers whole heads -> each (row, head)
// dot is produced by exactly one block: plain stores, no atomics.
// ----------------------------------------------------------------------------
template <int BN, int TN, int H>
__global__ __launch_bounds__(256, 2)
void sgemm_fused(const float* __restrict__ A, const float* __restrict__ B,
                 float* __restrict__ C, int M, int K, int Ncols,
                 const float* __restrict__ a_src, const float* __restrict__ a_dst,
                 float* __restrict__ als, float* __restrict__ ald) {
    const int BM = 128, BK = 8, TM = 8;
    __shared__ alignas(16) float As[2][BK][BM];
    __shared__ alignas(16) float Bs[2][BK][BN];

    int tid = threadIdx.x;
    int mBlock = blockIdx.x * BM;
    int nBlock = blockIdx.y * BN;

    const int TCOLS = BN / TN;    // 16
    int tcol = tid % TCOLS;
    int trow = tid / TCOLS;
    int lane = tid & 31;

    float acc[TM][TN];
#pragma unroll
    for (int i = 0; i < TM; i++)
#pragma unroll
        for (int j = 0; j < TN; j++) acc[i][j] = 0.f;

    int aRow = tid >> 1;
    int aCol = (tid & 1) * 4;
    int bRow = tid / (BN / 4);
    int bCol = (tid % (BN / 4)) * 4;
    bool bAct = (tid < 2 * BN);
    int gr = mBlock + aRow;
    bool aAct = (gr < M);

    // ---- preload stage 0 ----
    {
        float4 av = make_float4(0.f, 0.f, 0.f, 0.f);
        if (aAct) av = *(const float4*)(A + (size_t)gr * K + aCol);
        As[0][aCol + 0][aRow] = av.x;
        As[0][aCol + 1][aRow] = av.y;
        As[0][aCol + 2][aRow] = av.z;
        As[0][aCol + 3][aRow] = av.w;
        if (bAct) {
            float4 bv = *(const float4*)(B + (size_t)bRow * Ncols + nBlock + bCol);
            *(float4*)&Bs[0][bRow][bCol] = bv;
        }
    }
    __syncthreads();

    int buf = 0;
    for (int k0 = BK; k0 < K; k0 += BK) {
        // issue next-stage global loads
        float4 av = make_float4(0.f, 0.f, 0.f, 0.f);
        if (aAct) av = *(const float4*)(A + (size_t)gr * K + k0 + aCol);
        float4 bv;
        if (bAct) bv = *(const float4*)(B + (size_t)(k0 + bRow) * Ncols + nBlock + bCol);

        // compute on current buffer
#pragma unroll
        for (int kk = 0; kk < BK; kk++) {
            float ra[TM], rb[TN];
#pragma unroll
            for (int i = 0; i < TM; i++) ra[i] = As[buf][kk][trow * TM + i];
#pragma unroll
            for (int j = 0; j < TN; j++) rb[j] = Bs[buf][kk][tcol * TN + j];
#pragma unroll
            for (int i = 0; i < TM; i++)
#pragma unroll
                for (int j = 0; j < TN; j++) acc[i][j] += ra[i] * rb[j];
        }

        // store next stage
        As[buf ^ 1][aCol + 0][aRow] = av.x;
        As[buf ^ 1][aCol + 1][aRow] = av.y;
        As[buf ^ 1][aCol + 2][aRow] = av.z;
        As[buf ^ 1][aCol + 3][aRow] = av.w;
        if (bAct) *(float4*)&Bs[buf ^ 1][bRow][bCol] = bv;
        __syncthreads();
        buf ^= 1;
    }

    // last tile
#pragma unroll
    for (int kk = 0; kk < BK; kk++) {
        float ra[TM], rb[TN];
#pragma unroll
        for (int i = 0; i < TM; i++) ra[i] = As[buf][kk][trow * TM + i];
#pragma unroll
        for (int j = 0; j < TN; j++) rb[j] = Bs[buf][kk][tcol * TN + j];
#pragma unroll
        for (int i = 0; i < TM; i++)
#pragma unroll
            for (int j = 0; j < TN; j++) acc[i][j] += ra[i] * rb[j];
    }

    // ---- store C ----
#pragma unroll
    for (int i = 0; i < TM; i++) {
        int row = mBlock + trow * TM + i;
        if (row < M) {
            float* cp = C + (size_t)row * Ncols + nBlock + tcol * TN;
#pragma unroll
            for (int j = 0; j < TN; j++) cp[j] = acc[i][j];
        }
    }

    // ---- fused attention dots ----
    // RED = lanes covering one head's 64 columns (8 for TN=8, 16 for TN=4)
    const int RED = 64 / TN;
    int col0 = nBlock + tcol * TN;
    int head = col0 >> 6;

    float asv[TN], adv[TN];
#pragma unroll
    for (int j = 0; j < TN; j++) {
        asv[j] = a_src[col0 + j];
        adv[j] = a_dst[col0 + j];
    }

#pragma unroll
    for (int i = 0; i < TM; i++) {
        float d1 = 0.f, d2 = 0.f;
#pragma unroll
        for (int j = 0; j < TN; j++) {
            d1 += acc[i][j] * asv[j];
            d2 += acc[i][j] * adv[j];
        }
#pragma unroll
        for (int off = RED / 2; off > 0; off >>= 1) {
            d1 += __shfl_down_sync(0xffffffffu, d1, off);
            d2 += __shfl_down_sync(0xffffffffu, d2, off);
        }
        if ((lane & (RED - 1)) == 0) {
            int row = mBlock + trow * TM + i;
            if (row < M) {
                als[row * H + head] = d1;
                ald[row * H + head] = d2;
            }
        }
    }
}

// ----------------------------------------------------------------------------
// CSR gather-aggregate, H=4 C=64. Warp per dst node; 8 floats/lane.
// ----------------------------------------------------------------------------
__global__ void gat_agg4(const int* __restrict__ off, const int* __restrict__ csr,
                         const float* __restrict__ h,
                         const float* __restrict__ als, const float* __restrict__ ald,
                         const float4* __restrict__ bias, float* __restrict__ out) {
    int node = (blockIdx.x * blockDim.x + threadIdx.x) >> 5;
    int lane = threadIdx.x & 31;
    if (node >= NN) return;

    float Mg = fmaxf(0.f, g_maxs + g_maxd);
    int head = lane >> 3;
    float aldv = ald[node * 4 + head];

    float4 acc0 = make_float4(0.f, 0.f, 0.f, 0.f);
    float4 acc1 = make_float4(0.f, 0.f, 0.f, 0.f);
    float ssum = 0.f;

    int beg = off[node], end = off[node + 1];
    int i = beg;
    for (; i + 1 < end; i += 2) {
        int s0 = csr[i], s1 = csr[i + 1];
        float wt0 = __expf(lrelu(als[s0 * 4 + head] + aldv) - Mg);
        float wt1 = __expf(lrelu(als[s1 * 4 + head] + aldv) - Mg);
        const float4* h0 = (const float4*)(h + (size_t)s0 * 256 + lane * 8);
        const float4* h1 = (const float4*)(h + (size_t)s1 * 256 + lane * 8);
        float4 v00 = h0[0], v01 = h0[1];
        float4 v10 = h1[0], v11 = h1[1];
        ssum += wt0 + wt1;
        acc0.x += wt0 * v00.x + wt1 * v10.x;
        acc0.y += wt0 * v00.y + wt1 * v10.y;
        acc0.z += wt0 * v00.z + wt1 * v10.z;
        acc0.w += wt0 * v00.w + wt1 * v10.w;
        acc1.x += wt0 * v01.x + wt1 * v11.x;
        acc1.y += wt0 * v01.y + wt1 * v11.y;
        acc1.z += wt0 * v01.z + wt1 * v11.z;
        acc1.w += wt0 * v01.w + wt1 * v11.w;
    }
    if (i < end) {
        int s0 = csr[i];
        float wt0 = __expf(lrelu(als[s0 * 4 + head] + aldv) - Mg);
        const float4* h0 = (const float4*)(h + (size_t)s0 * 256 + lane * 8);
        float4 v00 = h0[0], v01 = h0[1];
        ssum += wt0;
        acc0.x += wt0 * v00.x; acc0.y += wt0 * v00.y;
        acc0.z += wt0 * v00.z; acc0.w += wt0 * v00.w;
        acc1.x += wt0 * v01.x; acc1.y += wt0 * v01.y;
        acc1.z += wt0 * v01.z; acc1.w += wt0 * v01.w;
    }

    float inv = 1.f / (ssum + EPSV);
    float4 b0 = bias[lane * 2];
    float4 b1 = bias[lane * 2 + 1];
    float4 r0, r1;
    r0.x = fmaxf(acc0.x * inv + b0.x, 0.f);
    r0.y = fmaxf(acc0.y * inv + b0.y, 0.f);
    r0.z = fmaxf(acc0.z * inv + b0.z, 0.f);
    r0.w = fmaxf(acc0.w * inv + b0.w, 0.f);
    r1.x = fmaxf(acc1.x * inv + b1.x, 0.f);
    r1.y = fmaxf(acc1.y * inv + b1.y, 0.f);
    r1.z = fmaxf(acc1.z * inv + b1.z, 0.f);
    r1.w = fmaxf(acc1.w * inv + b1.w, 0.f);
    float4* op = (float4*)(out + (size_t)node * 256 + lane * 8);
    op[0] = r0;
    op[1] = r1;
}

// CSR gather-aggregate, H=1 C=64
__global__ void gat_agg1(const int* __restrict__ off, const int* __restrict__ csr,
                         const float* __restrict__ h,
                         const float* __restrict__ als, const float* __restrict__ ald,
                         float* __restrict__ out) {
    int node = (blockIdx.x * blockDim.x + threadIdx.x) >> 5;
    int lane = threadIdx.x & 31;
    if (node >= NN) return;

    float Mg = fmaxf(0.f, g_maxs + g_maxd);
    float aldv = ald[node];

    float2 acc = make_float2(0.f, 0.f);
    float ssum = 0.f;

    int beg = off[node], end = off[node + 1];
    int i = beg;
    for (; i + 1 < end; i += 2) {
        int s0 = csr[i], s1 = csr[i + 1];
        float wt0 = __expf(lrelu(als[s0] + aldv) - Mg);
        float wt1 = __expf(lrelu(als[s1] + aldv) - Mg);
        float2 v0 = *(const float2*)(h + (size_t)s0 * 64 + lane * 2);
        float2 v1 = *(const float2*)(h + (size_t)s1 * 64 + lane * 2);
        ssum += wt0 + wt1;
        acc.x += wt0 * v0.x + wt1 * v1.x;
        acc.y += wt0 * v0.y + wt1 * v1.y;
    }
    if (i < end) {
        int s0 = csr[i];
        float wt0 = __expf(lrelu(als[s0] + aldv) - Mg);
        float2 v0 = *(const float2*)(h + (size_t)s0 * 64 + lane * 2);
        ssum += wt0;
        acc.x += wt0 * v0.x;
        acc.y += wt0 * v0.y;
    }

    float inv = 1.f / (ssum + EPSV);
    *(float2*)(out + (size_t)node * 64 + lane * 2) =
        make_float2(acc.x * inv, acc.y * inv);
}

// ----------------------------------------------------------------------------
// Pool + final
// ----------------------------------------------------------------------------
__global__ void zero_f4(float4* __restrict__ p, int n4) {
    int i = blockIdx.x * blockDim.x + threadIdx.x;
    int stride = gridDim.x * blockDim.x;
    float4 z = make_float4(0.f, 0.f, 0.f, 0.f);
    for (; i < n4; i += stride) p[i] = z;
}

__global__ void counts_k(const int* __restrict__ batch, float* __restrict__ cnt) {
    int g = threadIdx.x;
    if (g >= NGRAPH) return;
    int lo = 0, hi = NN;
    while (lo < hi) { int mid = (lo + hi) >> 1; if (batch[mid] < g) lo = mid + 1; else hi = mid; }
    int a = lo;
    lo = 0; hi = NN;
    while (lo < hi) { int mid = (lo + hi) >> 1; if (batch[mid] < g + 1) lo = mid + 1; else hi = mid; }
    cnt[g] = (float)(lo - a);
}

__global__ void pool_sum(const float* __restrict__ h, const int* __restrict__ batch,
                         float* __restrict__ pool) {
    int c = threadIdx.x & 63;
    int r = threadIdx.x >> 6;
    int start = blockIdx.x * 1024;
    int end = start + 1024;
    if (end > NN) end = NN;
    int cur = -1;
    float acc = 0.f;
    for (int nd = start + r; nd < end; nd += 4) {
        int g = batch[nd];
        if (g != cur) {
            if (cur >= 0) atomicAdd(&pool[cur * 64 + c], acc);
            cur = g;
            acc = 0.f;
        }
        acc += h[(size_t)nd * 64 + c];
    }
    if (cur >= 0) atomicAdd(&pool[cur * 64 + c], acc);
}

__global__ void final_k(const float* __restrict__ pool, const float* __restrict__ cnt,
                        const float* __restrict__ b3,
                        const float* __restrict__ linW, const float* __restrict__ linb,
                        float* __restrict__ out) {
    int g = blockIdx.x;
    int j = threadIdx.x;
    __shared__ float mean[64];
    float cc = fmaxf(cnt[g], 1.f);
    mean[j] = pool[g * 64 + j] / cc + b3[j];
    __syncthreads();
    float acc = 0.f;
#pragma unroll
    for (int k = 0; k < 64; k++) acc += mean[k] * linW[k * 64 + j];
    out[g * 64 + j] = acc + linb[j];
}

// ----------------------------------------------------------------------------
// Host launcher
// ----------------------------------------------------------------------------
extern "C" void kernel_launch(void* const* d_in, const int* in_sizes, int n_in,
                              void* d_out, int out_size) {
    const float* x     = (const float*)d_in[0];
    const void*  ei    = d_in[1];
    const void*  batch = d_in[3];
    const float* W1  = (const float*)d_in[4];
    const float* a1s = (const float*)d_in[5];
    const float* a1d = (const float*)d_in[6];
    const float* b1  = (const float*)d_in[7];
    const float* W2  = (const float*)d_in[8];
    const float* a2s = (const float*)d_in[9];
    const float* a2d = (const float*)d_in[10];
    const float* b2  = (const float*)d_in[11];
    const float* W3  = (const float*)d_in[12];
    const float* a3s = (const float*)d_in[13];
    const float* a3d = (const float*)d_in[14];
    const float* b3  = (const float*)d_in[15];
    const float* lW  = (const float*)d_in[16];
    const float* lb  = (const float*)d_in[17];
    float* out = (float*)d_out;

    float *p_h, *p_agg, *p_als, *p_ald, *p_pool, *p_cnt;
    int *p_src, *p_dst, *p_off, *p_cur, *p_csr, *p_batch;
    cudaGetSymbolAddress((void**)&p_h,    g_h);
    cudaGetSymbolAddress((void**)&p_agg,  g_agg);
    cudaGetSymbolAddress((void**)&p_als,  g_als);
    cudaGetSymbolAddress((void**)&p_ald,  g_ald);
    cudaGetSymbolAddress((void**)&p_src,  g_src);
    cudaGetSymbolAddress((void**)&p_dst,  g_dst);
    cudaGetSymbolAddress((void**)&p_off,  g_off);
    cudaGetSymbolAddress((void**)&p_cur,  g_cur);
    cudaGetSymbolAddress((void**)&p_csr,  g_csr);
    cudaGetSymbolAddress((void**)&p_batch,g_batch);
    cudaGetSymbolAddress((void**)&p_pool, g_pool);
    cudaGetSymbolAddress((void**)&p_cnt,  g_cnt);

    const int TB = 256;
    const int mTiles = (NN + 127) / 128;
    const int nodeWarpBlocks = (NN * 32 + TB - 1) / TB;

    // --- CSR build (once; reused across all 3 layers) ---
    detect_dtype<<<1, 32>>>((const unsigned int*)ei);
    zero_i<<<(NN + 1 + TB - 1) / TB, TB>>>(p_off, NN + 1);
    conv_edges<<<(NEDGE + TB - 1) / TB, TB>>>(ei, p_src, p_dst, p_off);
    conv_batch<<<(NN + TB - 1) / TB, TB>>>(batch, p_batch);
    scan_k<<<1, 1024>>>(p_off, NN + 1);
    set_cursors<<<(NN + TB - 1) / TB, TB>>>(p_off, p_cur);
    scatter_csr<<<(NEDGE + TB - 1) / TB, TB>>>(p_src, p_dst, p_cur, p_csr);

    // ================= Layer 1: 128 -> 4x64 =================
    {
        dim3 grid(mTiles, HC12 / 128);
        sgemm_fused<128, 8, 4><<<grid, TB>>>(x, W1, p_h, NN, 128, HC12,
                                             a1s, a1d, p_als, p_ald);
        init_max_k<<<1, 1>>>();
        max_reduce<<<200, TB>>>(p_als, p_ald, NN * 4);
        gat_agg4<<<nodeWarpBlocks, TB>>>(p_off, p_csr, p_h, p_als, p_ald,
                                         (const float4*)b1, p_agg);
    }

    // ================= Layer 2: 256 -> 4x64 =================
    {
        dim3 grid(mTiles, HC12 / 128);
        sgemm_fused<128, 8, 4><<<grid, TB>>>(p_agg, W2, p_h, NN, HC12, HC12,
                                             a2s, a2d, p_als, p_ald);
        init_max_k<<<1, 1>>>();
        max_reduce<<<200, TB>>>(p_als, p_ald, NN * 4);
        gat_agg4<<<nodeWarpBlocks, TB>>>(p_off, p_csr, p_h, p_als, p_ald,
                                         (const float4*)b2, p_agg);
    }

    // ================= Layer 3: 256 -> 1x64 =================
    {
        dim3 grid(mTiles, 1);
        sgemm_fused<64, 4, 1><<<grid, TB>>>(p_agg, W3, p_h, NN, HC12, HC3,
                                            a3s, a3d, p_als, p_ald);
        init_max_k<<<1, 1>>>();
        max_reduce<<<200, TB>>>(p_als, p_ald, NN);
        gat_agg1<<<nodeWarpBlocks, TB>>>(p_off, p_csr, p_h, p_als, p_ald, p_agg);
    }

    // ================= Pool + final linear =================
    zero_f4<<<4, 64>>>((float4*)p_pool, NGRAPH * HC3 / 4);
    counts_k<<<1, 64>>>(p_batch, p_cnt);
    pool_sum<<<(NN + 1023) / 1024, 256>>>(p_agg, p_batch, p_pool);
    final_k<<<NGRAPH, 64>>>(p_pool, p_cnt, b3, lW, lb, out);
}

// round 7
// speedup vs baseline: 2.1980x; 1.1147x over previous
#include <cuda_runtime.h>
#include <cuda_bf16.h>
#include <math.h>
#include <stdint.h>

// ----------------------------------------------------------------------------
// Problem constants
// ----------------------------------------------------------------------------
#define NN      50000
#define EE      800000
#define NEDGE   (EE + NN)       // with self loops = 850000
#define NGRAPH  64
#define HC12    256
#define HC3     64
#define NEG_SLOPE 0.2f
#define EPSV    1e-16f

// ----------------------------------------------------------------------------
// Device scratch
// ----------------------------------------------------------------------------
__device__ __align__(256) float g_h   [(size_t)NN * HC12];
__device__ __align__(256) float g_agg [(size_t)NN * HC12];
__device__ __align__(256) float g_als [NN * 4];
__device__ __align__(256) float g_ald [NN * 4];
__device__ __align__(256) int   g_src [NEDGE];
__device__ __align__(256) int   g_dst [NEDGE];
__device__ __align__(256) int   g_off [NN + 1];
__device__ __align__(256) int   g_cur [NN];
__device__ __align__(256) int   g_csr [NEDGE];
__device__ __align__(256) int   g_batch[NN];
__device__ __align__(256) float g_pool[NGRAPH * HC3];
__device__ __align__(256) float g_cnt [NGRAPH];
__device__ int   g_is64;
__device__ float g_maxs;
__device__ float g_maxd;

// ----------------------------------------------------------------------------
// Helpers
// ----------------------------------------------------------------------------
__device__ __forceinline__ float lrelu(float x) {
    return x >= 0.f ? x : NEG_SLOPE * x;
}
__device__ __forceinline__ void atomicMaxF(float* addr, float v) {
    if (v >= 0.f) atomicMax((int*)addr, __float_as_int(v));
    else          atomicMin((unsigned int*)addr, __float_as_uint(v));
}

// tf32 split: x -> hi (rna-rounded tf32) and lo (residual as tf32)
__device__ __forceinline__ void split_tf32(float x, uint32_t* hp, uint32_t* lp) {
    uint32_t h;
    asm("cvt.rna.tf32.f32 %0, %1;" : "=r"(h) : "f"(x));
    float r = x - __uint_as_float(h);
    uint32_t l;
    asm("cvt.rna.tf32.f32 %0, %1;" : "=r"(l) : "f"(r));
    *hp = h;
    *lp = l;
}

__device__ __forceinline__ void mma_tf32(float* c, const uint32_t* a,
                                         uint32_t b0, uint32_t b1) {
    asm volatile(
        "mma.sync.aligned.m16n8k8.row.col.f32.tf32.tf32.f32 "
        "{%0,%1,%2,%3}, {%4,%5,%6,%7}, {%8,%9}, {%0,%1,%2,%3};"
        : "+f"(c[0]), "+f"(c[1]), "+f"(c[2]), "+f"(c[3])
        : "r"(a[0]), "r"(a[1]), "r"(a[2]), "r"(a[3]), "r"(b0), "r"(b1));
}

// ----------------------------------------------------------------------------
// Dtype probe + CSR build
// ----------------------------------------------------------------------------
__global__ void detect_dtype(const unsigned int* __restrict__ w) {
    if (threadIdx.x == 0 && blockIdx.x == 0) {
        int all0 = 1;
        for (int i = 1; i < 128; i += 2)
            if (w[i] != 0u) { all0 = 0; break; }
        g_is64 = all0;
    }
}

__global__ void zero_i(int* __restrict__ p, int n) {
    int i = blockIdx.x * blockDim.x + threadIdx.x;
    if (i < n) p[i] = 0;
}

__global__ void conv_edges(const void* __restrict__ ei_raw,
                           int* __restrict__ src, int* __restrict__ dst,
                           int* __restrict__ off) {
    int i = blockIdx.x * blockDim.x + threadIdx.x;
    if (i >= NEDGE) return;
    int sv, dv;
    if (i >= EE) {
        sv = dv = i - EE;
    } else if (g_is64) {
        const long long* e = (const long long*)ei_raw;
        sv = (int)e[i];
        dv = (int)e[EE + i];
    } else {
        const int* e = (const int*)ei_raw;
        sv = e[i];
        dv = e[EE + i];
    }
    src[i] = sv;
    dst[i] = dv;
    atomicAdd(&off[dv + 1], 1);
}

__global__ void conv_batch(const void* __restrict__ b_raw, int* __restrict__ bo) {
    int i = blockIdx.x * blockDim.x + threadIdx.x;
    if (i >= NN) return;
    bo[i] = g_is64 ? (int)((const long long*)b_raw)[i] : ((const int*)b_raw)[i];
}

__global__ void scan_k(int* __restrict__ a, int n) {
    __shared__ int warp_sums[32];
    __shared__ int carry_s;
    int tid = threadIdx.x, lane = tid & 31, wid = tid >> 5;
    if (tid == 0) carry_s = 0;
    __syncthreads();
    for (int base = 0; base < n; base += 1024) {
        int idx = base + tid;
        int v = (idx < n) ? a[idx] : 0;
#pragma unroll
        for (int off = 1; off < 32; off <<= 1) {
            int t = __shfl_up_sync(0xffffffffu, v, off);
            if (lane >= off) v += t;
        }
        if (lane == 31) warp_sums[wid] = v;
        __syncthreads();
        if (wid == 0) {
            int w = warp_sums[lane];
#pragma unroll
            for (int off = 1; off < 32; off <<= 1) {
                int t = __shfl_up_sync(0xffffffffu, w, off);
                if (lane >= off) w += t;
            }
            warp_sums[lane] = w;
        }
        __syncthreads();
        int add = (wid > 0 ? warp_sums[wid - 1] : 0) + carry_s;
        if (idx < n) a[idx] = v + add;
        int total = warp_sums[31];
        __syncthreads();
        if (tid == 0) carry_s += total;
        __syncthreads();
    }
}

__global__ void set_cursors(const int* __restrict__ off, int* __restrict__ cur) {
    int i = blockIdx.x * blockDim.x + threadIdx.x;
    if (i < NN) cur[i] = off[i];
}

__global__ void scatter_csr(const int* __restrict__ src, const int* __restrict__ dst,
                            int* __restrict__ cur, int* __restrict__ csr) {
    int i = blockIdx.x * blockDim.x + threadIdx.x;
    if (i >= NEDGE) return;
    int pos = atomicAdd(&cur[dst[i]], 1);
    csr[pos] = src[i];
}

__global__ void init_max_k() {
    g_maxs = -INFINITY;
    g_maxd = -INFINITY;
}

__global__ void max_reduce(const float* __restrict__ als, const float* __restrict__ ald,
                           int n) {
    __shared__ float sm1[8], sm2[8];
    int lane = threadIdx.x & 31, wib = threadIdx.x >> 5;
    float m1 = -INFINITY, m2 = -INFINITY;
    for (int i = blockIdx.x * blockDim.x + threadIdx.x; i < n;
         i += gridDim.x * blockDim.x) {
        m1 = fmaxf(m1, als[i]);
        m2 = fmaxf(m2, ald[i]);
    }
#pragma unroll
    for (int off = 16; off > 0; off >>= 1) {
        m1 = fmaxf(m1, __shfl_down_sync(0xffffffffu, m1, off));
        m2 = fmaxf(m2, __shfl_down_sync(0xffffffffu, m2, off));
    }
    if (lane == 0) { sm1[wib] = m1; sm2[wib] = m2; }
    __syncthreads();
    if (threadIdx.x == 0) {
        for (int i = 1; i < (int)(blockDim.x >> 5); i++) {
            m1 = fmaxf(m1, sm1[i]);
            m2 = fmaxf(m2, sm2[i]);
        }
        atomicMaxF(&g_maxs, m1);
        atomicMaxF(&g_maxd, m2);
    }
}

// ----------------------------------------------------------------------------
// 3xTF32 tensor-core GEMM with fused attention-dot epilogue.
// C[M,Ncols] = A[M,K] @ B[K,Ncols] (fp32 in/out, 3xtf32 internally).
// BM=128, BK=16. 256 threads = 8 warps.
//   BN=128: warp grid 4(m) x 2(n), warp tile 32x64   (layers 1,2)
//   BN=64 : warp grid 8(m) x 1(n), warp tile 16x64   (layer 3)
// Each warp covers exactly one 64-column head -> per-row attention dots are
// reduced within 4-lane groups (shfl_xor) and stored without atomics.
// ----------------------------------------------------------------------------
template <int BN, int H>
__global__ __launch_bounds__(256, 2)
void mma_gemm_fused(const float* __restrict__ A, const float* __restrict__ B,
                    float* __restrict__ C, int M, int K, int Ncols,
                    const float* __restrict__ a_src, const float* __restrict__ a_dst,
                    float* __restrict__ als, float* __restrict__ ald) {
    const int BM = 128, BK = 16;
    const int WARPS_N = BN / 64;
    const int WARPS_M = 8 / WARPS_N;
    const int WROWS = BM / WARPS_M;      // 32 or 16
    const int MT = WROWS / 16;           // 2 or 1
    const int AS = BM + 8;               // padded strides (bank shift 8)
    const int BS = BN + 8;

    __shared__ uint32_t As_hi[BK][AS], As_lo[BK][AS];
    __shared__ uint32_t Bs_hi[BK][BS], Bs_lo[BK][BS];

    int tid = threadIdx.x;
    int wid = tid >> 5;
    int lane = tid & 31;
    int lm = lane >> 2;   // groupID 0..7
    int lk = lane & 3;    // threadID in group

    int warpN = wid % WARPS_N;
    int warpM = wid / WARPS_N;

    int mBlock = blockIdx.x * BM;
    int nBlock = blockIdx.y * BN;

    float c[MT][8][4];
#pragma unroll
    for (int i = 0; i < MT; i++)
#pragma unroll
        for (int j = 0; j < 8; j++)
#pragma unroll
            for (int q = 0; q < 4; q++) c[i][j][q] = 0.f;

    // global->smem mapping (A): thread covers row tid>>1, cols (tid&1)*8..+7
    int aRow = tid >> 1;
    int aColB = (tid & 1) * 8;
    int gr = mBlock + aRow;
    bool aAct = (gr < M);

    for (int k0 = 0; k0 < K; k0 += BK) {
        // ---- A tile ----
        {
            float4 v0 = make_float4(0.f, 0.f, 0.f, 0.f), v1 = v0;
            if (aAct) {
                const float* ap = A + (size_t)gr * K + k0 + aColB;
                v0 = *(const float4*)ap;
                v1 = *(const float4*)(ap + 4);
            }
            float av[8] = {v0.x, v0.y, v0.z, v0.w, v1.x, v1.y, v1.z, v1.w};
#pragma unroll
            for (int q = 0; q < 8; q++)
                split_tf32(av[q], &As_hi[aColB + q][aRow], &As_lo[aColB + q][aRow]);
        }
        // ---- B tile ----
        if (BN == 128) {
            int row = tid >> 5;           // 0..7
            int col4 = tid & 31;          // 0..31
#pragma unroll
            for (int rr = 0; rr < 2; rr++) {
                int r = row + rr * 8;
                const float* bp = B + (size_t)(k0 + r) * Ncols + nBlock + col4 * 4;
                float4 v = *(const float4*)bp;
                float bv[4] = {v.x, v.y, v.z, v.w};
#pragma unroll
                for (int q = 0; q < 4; q++)
                    split_tf32(bv[q], &Bs_hi[r][col4 * 4 + q], &Bs_lo[r][col4 * 4 + q]);
            }
        } else {
            int row = tid >> 4;           // 0..15
            int col4 = tid & 15;          // 0..15
            const float* bp = B + (size_t)(k0 + row) * Ncols + nBlock + col4 * 4;
            float4 v = *(const float4*)bp;
            float bv[4] = {v.x, v.y, v.z, v.w};
#pragma unroll
            for (int q = 0; q < 4; q++)
                split_tf32(bv[q], &Bs_hi[row][col4 * 4 + q], &Bs_lo[row][col4 * 4 + q]);
        }
        __syncthreads();

        // ---- compute: 2 k8-steps per stage ----
#pragma unroll
        for (int kk = 0; kk < BK; kk += 8) {
#pragma unroll
            for (int i = 0; i < MT; i++) {
                int m0 = warpM * WROWS + i * 16 + lm;
                uint32_t ah[4], al[4];
                ah[0] = As_hi[kk + lk][m0];     ah[1] = As_hi[kk + lk][m0 + 8];
                ah[2] = As_hi[kk + lk + 4][m0]; ah[3] = As_hi[kk + lk + 4][m0 + 8];
                al[0] = As_lo[kk + lk][m0];     al[1] = As_lo[kk + lk][m0 + 8];
                al[2] = As_lo[kk + lk + 4][m0]; al[3] = As_lo[kk + lk + 4][m0 + 8];
#pragma unroll
                for (int j = 0; j < 8; j++) {
                    int n0 = warpN * 64 + j * 8 + lm;
                    uint32_t bh0 = Bs_hi[kk + lk][n0];
                    uint32_t bh1 = Bs_hi[kk + lk + 4][n0];
                    uint32_t bl0 = Bs_lo[kk + lk][n0];
                    uint32_t bl1 = Bs_lo[kk + lk + 4][n0];
                    mma_tf32(c[i][j], ah, bh0, bh1);
                    mma_tf32(c[i][j], ah, bl0, bl1);
                    mma_tf32(c[i][j], al, bh0, bh1);
                }
            }
        }
        __syncthreads();
    }

    // ---- epilogue: store C + fused attention dots ----
    int head_base = nBlock + warpN * 64;
    int head = head_base >> 6;

#pragma unroll
    for (int i = 0; i < MT; i++) {
        int r0 = mBlock + warpM * WROWS + i * 16 + lm;
        int r1 = r0 + 8;
        float d1a = 0.f, d2a = 0.f, d1b = 0.f, d2b = 0.f;
#pragma unroll
        for (int j = 0; j < 8; j++) {
            int colg = head_base + j * 8 + lk * 2;
            float as0 = a_src[colg], as1 = a_src[colg + 1];
            float ad0 = a_dst[colg], ad1 = a_dst[colg + 1];
            float* cc = c[i][j];
            d1a += cc[0] * as0 + cc[1] * as1;
            d2a += cc[0] * ad0 + cc[1] * ad1;
            d1b += cc[2] * as0 + cc[3] * as1;
            d2b += cc[2] * ad0 + cc[3] * ad1;
            if (r0 < M) *(float2*)&C[(size_t)r0 * Ncols + colg] = make_float2(cc[0], cc[1]);
            if (r1 < M) *(float2*)&C[(size_t)r1 * Ncols + colg] = make_float2(cc[2], cc[3]);
        }
#pragma unroll
        for (int off = 1; off <= 2; off <<= 1) {
            d1a += __shfl_xor_sync(0xffffffffu, d1a, off);
            d2a += __shfl_xor_sync(0xffffffffu, d2a, off);
            d1b += __shfl_xor_sync(0xffffffffu, d1b, off);
            d2b += __shfl_xor_sync(0xffffffffu, d2b, off);
        }
        if (lk == 0) {
            if (r0 < M) { als[r0 * H + head] = d1a; ald[r0 * H + head] = d2a; }
            if (r1 < M) { als[r1 * H + head] = d1b; ald[r1 * H + head] = d2b; }
        }
    }
}

// ----------------------------------------------------------------------------
// CSR gather-aggregate, H=4 C=64. Warp per dst node; 8 floats/lane.
// ----------------------------------------------------------------------------
__global__ void gat_agg4(const int* __restrict__ off, const int* __restrict__ csr,
                         const float* __restrict__ h,
                         const float* __restrict__ als, const float* __restrict__ ald,
                         const float4* __restrict__ bias, float* __restrict__ out) {
    int node = (blockIdx.x * blockDim.x + threadIdx.x) >> 5;
    int lane = threadIdx.x & 31;
    if (node >= NN) return;

    float Mg = fmaxf(0.f, g_maxs + g_maxd);
    int head = lane >> 3;
    float aldv = ald[node * 4 + head];

    float4 acc0 = make_float4(0.f, 0.f, 0.f, 0.f);
    float4 acc1 = make_float4(0.f, 0.f, 0.f, 0.f);
    float ssum = 0.f;

    int beg = off[node], end = off[node + 1];
    int i = beg;
    for (; i + 1 < end; i += 2) {
        int s0 = csr[i], s1 = csr[i + 1];
        float wt0 = __expf(lrelu(als[s0 * 4 + head] + aldv) - Mg);
        float wt1 = __expf(lrelu(als[s1 * 4 + head] + aldv) - Mg);
        const float4* h0 = (const float4*)(h + (size_t)s0 * 256 + lane * 8);
        const float4* h1 = (const float4*)(h + (size_t)s1 * 256 + lane * 8);
        float4 v00 = h0[0], v01 = h0[1];
        float4 v10 = h1[0], v11 = h1[1];
        ssum += wt0 + wt1;
        acc0.x += wt0 * v00.x + wt1 * v10.x;
        acc0.y += wt0 * v00.y + wt1 * v10.y;
        acc0.z += wt0 * v00.z + wt1 * v10.z;
        acc0.w += wt0 * v00.w + wt1 * v10.w;
        acc1.x += wt0 * v01.x + wt1 * v11.x;
        acc1.y += wt0 * v01.y + wt1 * v11.y;
        acc1.z += wt0 * v01.z + wt1 * v11.z;
        acc1.w += wt0 * v01.w + wt1 * v11.w;
    }
    if (i < end) {
        int s0 = csr[i];
        float wt0 = __expf(lrelu(als[s0 * 4 + head] + aldv) - Mg);
        const float4* h0 = (const float4*)(h + (size_t)s0 * 256 + lane * 8);
        float4 v00 = h0[0], v01 = h0[1];
        ssum += wt0;
        acc0.x += wt0 * v00.x; acc0.y += wt0 * v00.y;
        acc0.z += wt0 * v00.z; acc0.w += wt0 * v00.w;
        acc1.x += wt0 * v01.x; acc1.y += wt0 * v01.y;
        acc1.z += wt0 * v01.z; acc1.w += wt0 * v01.w;
    }

    float inv = 1.f / (ssum + EPSV);
    float4 b0 = bias[lane * 2];
    float4 b1 = bias[lane * 2 + 1];
    float4 r0, r1;
    r0.x = fmaxf(acc0.x * inv + b0.x, 0.f);
    r0.y = fmaxf(acc0.y * inv + b0.y, 0.f);
    r0.z = fmaxf(acc0.z * inv + b0.z, 0.f);
    r0.w = fmaxf(acc0.w * inv + b0.w, 0.f);
    r1.x = fmaxf(acc1.x * inv + b1.x, 0.f);
    r1.y = fmaxf(acc1.y * inv + b1.y, 0.f);
    r1.z = fmaxf(acc1.z * inv + b1.z, 0.f);
    r1.w = fmaxf(acc1.w * inv + b1.w, 0.f);
    float4* op = (float4*)(out + (size_t)node * 256 + lane * 8);
    op[0] = r0;
    op[1] = r1;
}

// CSR gather-aggregate, H=1 C=64
__global__ void gat_agg1(const int* __restrict__ off, const int* __restrict__ csr,
                         const float* __restrict__ h,
                         const float* __restrict__ als, const float* __restrict__ ald,
                         float* __restrict__ out) {
    int node = (blockIdx.x * blockDim.x + threadIdx.x) >> 5;
    int lane = threadIdx.x & 31;
    if (node >= NN) return;

    float Mg = fmaxf(0.f, g_maxs + g_maxd);
    float aldv = ald[node];

    float2 acc = make_float2(0.f, 0.f);
    float ssum = 0.f;

    int beg = off[node], end = off[node + 1];
    int i = beg;
    for (; i + 1 < end; i += 2) {
        int s0 = csr[i], s1 = csr[i + 1];
        float wt0 = __expf(lrelu(als[s0] + aldv) - Mg);
        float wt1 = __expf(lrelu(als[s1] + aldv) - Mg);
        float2 v0 = *(const float2*)(h + (size_t)s0 * 64 + lane * 2);
        float2 v1 = *(const float2*)(h + (size_t)s1 * 64 + lane * 2);
        ssum += wt0 + wt1;
        acc.x += wt0 * v0.x + wt1 * v1.x;
        acc.y += wt0 * v0.y + wt1 * v1.y;
    }
    if (i < end) {
        int s0 = csr[i];
        float wt0 = __expf(lrelu(als[s0] + aldv) - Mg);
        float2 v0 = *(const float2*)(h + (size_t)s0 * 64 + lane * 2);
        ssum += wt0;
        acc.x += wt0 * v0.x;
        acc.y += wt0 * v0.y;
    }

    float inv = 1.f / (ssum + EPSV);
    *(float2*)(out + (size_t)node * 64 + lane * 2) =
        make_float2(acc.x * inv, acc.y * inv);
}

// ----------------------------------------------------------------------------
// Pool + final
// ----------------------------------------------------------------------------
__global__ void zero_f4(float4* __restrict__ p, int n4) {
    int i = blockIdx.x * blockDim.x + threadIdx.x;
    int stride = gridDim.x * blockDim.x;
    float4 z = make_float4(0.f, 0.f, 0.f, 0.f);
    for (; i < n4; i += stride) p[i] = z;
}

__global__ void counts_k(const int* __restrict__ batch, float* __restrict__ cnt) {
    int g = threadIdx.x;
    if (g >= NGRAPH) return;
    int lo = 0, hi = NN;
    while (lo < hi) { int mid = (lo + hi) >> 1; if (batch[mid] < g) lo = mid + 1; else hi = mid; }
    int a = lo;
    lo = 0; hi = NN;
    while (lo < hi) { int mid = (lo + hi) >> 1; if (batch[mid] < g + 1) lo = mid + 1; else hi = mid; }
    cnt[g] = (float)(lo - a);
}

__global__ void pool_sum(const float* __restrict__ h, const int* __restrict__ batch,
                         float* __restrict__ pool) {
    int c = threadIdx.x & 63;
    int r = threadIdx.x >> 6;
    int start = blockIdx.x * 1024;
    int end = start + 1024;
    if (end > NN) end = NN;
    int cur = -1;
    float acc = 0.f;
    for (int nd = start + r; nd < end; nd += 4) {
        int g = batch[nd];
        if (g != cur) {
            if (cur >= 0) atomicAdd(&pool[cur * 64 + c], acc);
            cur = g;
            acc = 0.f;
        }
        acc += h[(size_t)nd * 64 + c];
    }
    if (cur >= 0) atomicAdd(&pool[cur * 64 + c], acc);
}

__global__ void final_k(const float* __restrict__ pool, const float* __restrict__ cnt,
                        const float* __restrict__ b3,
                        const float* __restrict__ linW, const float* __restrict__ linb,
                        float* __restrict__ out) {
    int g = blockIdx.x;
    int j = threadIdx.x;
    __shared__ float mean[64];
    float cc = fmaxf(cnt[g], 1.f);
    mean[j] = pool[g * 64 + j] / cc + b3[j];
    __syncthreads();
    float acc = 0.f;
#pragma unroll
    for (int k = 0; k < 64; k++) acc += mean[k] * linW[k * 64 + j];
    out[g * 64 + j] = acc + linb[j];
}

// ----------------------------------------------------------------------------
// Host launcher
// ----------------------------------------------------------------------------
extern "C" void kernel_launch(void* const* d_in, const int* in_sizes, int n_in,
                              void* d_out, int out_size) {
    const float* x     = (const float*)d_in[0];
    const void*  ei    = d_in[1];
    const void*  batch = d_in[3];
    const float* W1  = (const float*)d_in[4];
    const float* a1s = (const float*)d_in[5];
    const float* a1d = (const float*)d_in[6];
    const float* b1  = (const float*)d_in[7];
    const float* W2  = (const float*)d_in[8];
    const float* a2s = (const float*)d_in[9];
    const float* a2d = (const float*)d_in[10];
    const float* b2  = (const float*)d_in[11];
    const float* W3  = (const float*)d_in[12];
    const float* a3s = (const float*)d_in[13];
    const float* a3d = (const float*)d_in[14];
    const float* b3  = (const float*)d_in[15];
    const float* lW  = (const float*)d_in[16];
    const float* lb  = (const float*)d_in[17];
    float* out = (float*)d_out;

    float *p_h, *p_agg, *p_als, *p_ald, *p_pool, *p_cnt;
    int *p_src, *p_dst, *p_off, *p_cur, *p_csr, *p_batch;
    cudaGetSymbolAddress((void**)&p_h,    g_h);
    cudaGetSymbolAddress((void**)&p_agg,  g_agg);
    cudaGetSymbolAddress((void**)&p_als,  g_als);
    cudaGetSymbolAddress((void**)&p_ald,  g_ald);
    cudaGetSymbolAddress((void**)&p_src,  g_src);
    cudaGetSymbolAddress((void**)&p_dst,  g_dst);
    cudaGetSymbolAddress((void**)&p_off,  g_off);
    cudaGetSymbolAddress((void**)&p_cur,  g_cur);
    cudaGetSymbolAddress((void**)&p_csr,  g_csr);
    cudaGetSymbolAddress((void**)&p_batch,g_batch);
    cudaGetSymbolAddress((void**)&p_pool, g_pool);
    cudaGetSymbolAddress((void**)&p_cnt,  g_cnt);

    const int TB = 256;
    const int mTiles = (NN + 127) / 128;    // 391
    const int nodeWarpBlocks = (NN * 32 + TB - 1) / TB;

    // --- CSR build (once; reused across all 3 layers) ---
    detect_dtype<<<1, 32>>>((const unsigned int*)ei);
    zero_i<<<(NN + 1 + TB - 1) / TB, TB>>>(p_off, NN + 1);
    conv_edges<<<(NEDGE + TB - 1) / TB, TB>>>(ei, p_src, p_dst, p_off);
    conv_batch<<<(NN + TB - 1) / TB, TB>>>(batch, p_batch);
    scan_k<<<1, 1024>>>(p_off, NN + 1);
    set_cursors<<<(NN + TB - 1) / TB, TB>>>(p_off, p_cur);
    scatter_csr<<<(NEDGE + TB - 1) / TB, TB>>>(p_src, p_dst, p_cur, p_csr);

    // ================= Layer 1: 128 -> 4x64 =================
    {
        dim3 grid(mTiles, HC12 / 128);
        mma_gemm_fused<128, 4><<<grid, TB>>>(x, W1, p_h, NN, 128, HC12,
                                             a1s, a1d, p_als, p_ald);
        init_max_k<<<1, 1>>>();
        max_reduce<<<200, TB>>>(p_als, p_ald, NN * 4);
        gat_agg4<<<nodeWarpBlocks, TB>>>(p_off, p_csr, p_h, p_als, p_ald,
                                         (const float4*)b1, p_agg);
    }

    // ================= Layer 2: 256 -> 4x64 =================
    {
        dim3 grid(mTiles, HC12 / 128);
        mma_gemm_fused<128, 4><<<grid, TB>>>(p_agg, W2, p_h, NN, HC12, HC12,
                                             a2s, a2d, p_als, p_ald);
        init_max_k<<<1, 1>>>();
        max_reduce<<<200, TB>>>(p_als, p_ald, NN * 4);
        gat_agg4<<<nodeWarpBlocks, TB>>>(p_off, p_csr, p_h, p_als, p_ald,
                                         (const float4*)b2, p_agg);
    }

    // ================= Layer 3: 256 -> 1x64 =================
    {
        dim3 grid(mTiles, 1);
        mma_gemm_fused<64, 1><<<grid, TB>>>(p_agg, W3, p_h, NN, HC12, HC3,
                                            a3s, a3d, p_als, p_ald);
        init_max_k<<<1, 1>>>();
        max_reduce<<<200, TB>>>(p_als, p_ald, NN);
        gat_agg1<<<nodeWarpBlocks, TB>>>(p_off, p_csr, p_h, p_als, p_ald, p_agg);
    }

    // ================= Pool + final linear =================
    zero_f4<<<4, 64>>>((float4*)p_pool, NGRAPH * HC3 / 4);
    counts_k<<<1, 64>>>(p_batch, p_cnt);
    pool_sum<<<(NN + 1023) / 1024, 256>>>(p_agg, p_batch, p_pool);
    final_k<<<NGRAPH, 64>>>(p_pool, p_cnt, b3, lW, lb, out);
}